// round 13
// baseline (speedup 1.0000x reference)
#include <cuda_runtime.h>
#include <cuda_fp16.h>
#include <cuda_bf16.h>
#include <cstdint>

#define MAXN 100000
#define MAXE 3200000
#define MAXF 128

#define W2_OFF (256 * 128)
#define W3_OFF (256 * 128 + 128 * 64)
#define WTOT   (256 * 128 + 128 * 64 + 64 * 32)

// stats regions: [0,256) layer1 (F=128), [256,384) layer2 (F=64), [384,448) layer3 (F=32)
#define ST2 256
#define ST3 384
#define STTOT 448

// Scratch (device globals; no cudaMalloc allowed)
__device__ float  g_agg[(size_t)MAXN * MAXF];        // fp32 aggregation output
__device__ __half g_h16[(size_t)MAXN * MAXF];        // fp16 dis-prescaled features
__device__ float  g_dis[MAXN];
__device__ int    g_deg[MAXN];
__device__ int    g_rowptr[MAXN + 1];
__device__ int    g_cursor[MAXN + 1];
__device__ int    g_bsum[256];
__device__ int    g_csr_src[MAXE];
__device__ float  g_stats[STTOT];
__device__ __half g_whi[WTOT];

// ---------------------------------------------------------------------------
// Prologue 1: fused degree count + weight fp16 round/transpose
// ---------------------------------------------------------------------------
__global__ void k_pro1(const int* __restrict__ ei, int* __restrict__ deg, int E, int nsc,
                       const float* __restrict__ W1, const float* __restrict__ W2,
                       const float* __restrict__ W3, __half* __restrict__ Wh)
{
    if ((int)blockIdx.x < nsc) {
        int e = blockIdx.x * 256 + threadIdx.x;
        if (e < E) atomicAdd(&deg[__ldg(ei + E + e)], 1);
        return;
    }
    int i = (blockIdx.x - nsc) * 256 + threadIdx.x;
    const float* W;
    int K, Nn, off, li;
    if (i < W2_OFF)       { W = W1; K = 256; Nn = 128; off = 0;      li = i; }
    else if (i < W3_OFF)  { W = W2; K = 128; Nn = 64;  off = W2_OFF; li = i - W2_OFF; }
    else if (i < WTOT)    { W = W3; K = 64;  Nn = 32;  off = W3_OFF; li = i - W3_OFF; }
    else return;
    int n = li / K, k = li - n * K;
    Wh[off + li] = __float2half_rn(__ldg(W + (size_t)k * Nn + n));
}

// ---------------------------------------------------------------------------
// Scan (exclusive) of deg -> rowptr; also emits dis = rsqrt(deg+1)
// ---------------------------------------------------------------------------
__global__ void k_scan_block(const int* __restrict__ deg, int* __restrict__ exc,
                             int* __restrict__ bsum, float* __restrict__ dis, int N)
{
    __shared__ int sh[1024];
    int i = blockIdx.x * 1024 + threadIdx.x;
    int v = (i < N) ? deg[i] : 0;
    sh[threadIdx.x] = v;
    __syncthreads();
#pragma unroll
    for (int o = 1; o < 1024; o <<= 1) {
        int t = (threadIdx.x >= o) ? sh[threadIdx.x - o] : 0;
        __syncthreads();
        sh[threadIdx.x] += t;
        __syncthreads();
    }
    if (i < N) {
        exc[i] = sh[threadIdx.x] - v;
        dis[i] = rsqrtf((float)v + 1.0f);
    }
    if (threadIdx.x == 1023) bsum[blockIdx.x] = sh[1023];
}

// Adds block offsets (bsum scanned redundantly per block in smem),
// mirrors rowptr->cursor, zeroes ALL BN stats regions.
__global__ void k_scan_add2(int* __restrict__ rowptr, int* __restrict__ cursor,
                            const int* __restrict__ bsum, float* __restrict__ stats,
                            int nb, int N)
{
    __shared__ int sh[256];
    __shared__ int sexc[256];
    int t = threadIdx.x;
    int v = (t < nb) ? __ldg(bsum + t) : 0;
    sh[t] = v;
    __syncthreads();
#pragma unroll
    for (int o = 1; o < 256; o <<= 1) {
        int u = (t >= o) ? sh[t - o] : 0;
        __syncthreads();
        sh[t] += u;
        __syncthreads();
    }
    sexc[t] = sh[t] - v;   // exclusive prefix of bsum
    __syncthreads();

    int i = blockIdx.x * 256 + t;
    if (i < N) {
        int val = rowptr[i] + sexc[i >> 10];
        rowptr[i] = val;
        cursor[i] = val;
    }
    if (blockIdx.x == 0) {
        for (int f = t; f < STTOT; f += 256) stats[f] = 0.0f;
    }
}

// ---------------------------------------------------------------------------
// MMA / ldmatrix / cp.async helpers
// ---------------------------------------------------------------------------
__device__ __forceinline__ void mma16816(float* c, const uint32_t* a, const uint32_t* b)
{
    asm volatile(
        "mma.sync.aligned.m16n8k16.row.col.f32.f16.f16.f32 "
        "{%0,%1,%2,%3}, {%4,%5,%6,%7}, {%8,%9}, {%0,%1,%2,%3};"
        : "+f"(c[0]), "+f"(c[1]), "+f"(c[2]), "+f"(c[3])
        : "r"(a[0]), "r"(a[1]), "r"(a[2]), "r"(a[3]), "r"(b[0]), "r"(b[1]));
}
__device__ __forceinline__ void ldsm_x4(uint32_t* r, uint32_t addr)
{
    asm volatile("ldmatrix.sync.aligned.m8n8.x4.shared.b16 {%0,%1,%2,%3}, [%4];"
                 : "=r"(r[0]), "=r"(r[1]), "=r"(r[2]), "=r"(r[3]) : "r"(addr));
}
__device__ __forceinline__ void ldsm_x2(uint32_t* r, uint32_t addr)
{
    asm volatile("ldmatrix.sync.aligned.m8n8.x2.shared.b16 {%0,%1}, [%2];"
                 : "=r"(r[0]), "=r"(r[1]) : "r"(addr));
}
__device__ __forceinline__ void cp_async16(uint32_t smem_addr, const void* gptr)
{
    asm volatile("cp.async.cg.shared.global [%0], [%1], 16;"
                 :: "r"(smem_addr), "l"(gptr) : "memory");
}
__device__ __forceinline__ void cp_commit() { asm volatile("cp.async.commit_group;" ::: "memory"); }
__device__ __forceinline__ void cp_wait0()  { asm volatile("cp.async.wait_group 0;"  ::: "memory"); }

// ---------------------------------------------------------------------------
// 2-product split GEMM core (A fp32, hi/lo split; W fp16-rounded).
// Double-buffered smem pipeline, ONE __syncthreads per k-tile:
//   - cp.async stages B(k+1) while tile k computes
//   - A(k+1) LDGs issued before compute, converted/stored after
//   C16[M,BN] = half( dis[m] * (BNReLU?(A[M,K]) @ W16[K,BN]) )
// BM=64, BK=32, 256 threads (8 warps 2x4), warp tile 32 x (BN/4).
// ---------------------------------------------------------------------------
template <int BN>
__device__ __forceinline__ void gemm_body(
    int bid, const float* __restrict__ A, const __half* __restrict__ Wh,
    __half* __restrict__ C16, const float* __restrict__ disv, int M, int K,
    const float* __restrict__ stats, const float* __restrict__ gam,
    const float* __restrict__ bt)
{
    constexpr int BM = 64, BK = 32;
    constexpr int LDA = BK + 8;           // halfs; 80B row stride
    constexpr int MT = 2;
    constexpr int NT = BN / 32;
    constexpr int WNW = BN / 4;
    constexpr int BCH = BN * 4;           // 16B chunks per B tile

    __shared__ __align__(16) __half Ah[2][BM][LDA];
    __shared__ __align__(16) __half Al[2][BM][LDA];
    __shared__ __align__(16) __half Bh[2][BN][LDA];
    __shared__ __align__(16) float bnp_s[512];   // [K] scale | [K] shift

    const int tid  = threadIdx.x;
    const int warp = tid >> 5;
    const int lane = tid & 31;
    const int g    = lane >> 2;
    const int t4   = lane & 3;
    const int wmi  = warp & 1;
    const int wni  = warp >> 1;
    const int m0   = bid * BM;
    const bool has_bn = (stats != nullptr);

    uint32_t ah_base[2], al_base[2], bh_base[2];
#pragma unroll
    for (int s = 0; s < 2; s++) {
        ah_base[s] = (uint32_t)__cvta_generic_to_shared(&Ah[s][0][0]);
        al_base[s] = (uint32_t)__cvta_generic_to_shared(&Al[s][0][0]);
        bh_base[s] = (uint32_t)__cvta_generic_to_shared(&Bh[s][0][0]);
    }
    const int arow = lane & 15;
    const int acol = (lane & 16) ? 8 : 0;
    const int brow = lane & 7;
    const int bcol = (lane & 8) ? 8 : 0;

    if (has_bn) {
        float inv_n = 1.0f / (float)M;
        for (int f = tid; f < K; f += 256) {
            float mu  = stats[f] * inv_n;
            float var = fmaxf(stats[K + f] * inv_n - mu * mu, 0.0f);
            float sc  = gam[f] * rsqrtf(var + 1e-5f);
            bnp_s[f]     = sc;
            bnp_s[K + f] = bt[f] - mu * sc;
        }
        __syncthreads();
    }

    // A staging: 64x32 floats = 512 float4, 2 per thread
    const int a_row0 = tid >> 3;
    const int a_row1 = (tid + 256) >> 3;
    const int a_c4   = tid & 7;

    auto ldA = [&](int k0, float4* r) {
        int gr0 = m0 + a_row0;
        int gr1 = m0 + a_row1;
        r[0] = (gr0 < M) ? *(const float4*)(A + (size_t)gr0 * K + k0 + a_c4 * 4)
                         : make_float4(0.f, 0.f, 0.f, 0.f);
        r[1] = (gr1 < M) ? *(const float4*)(A + (size_t)gr1 * K + k0 + a_c4 * 4)
                         : make_float4(0.f, 0.f, 0.f, 0.f);
    };
    auto stA = [&](float4* r, int k0, int s) {
#pragma unroll
        for (int i = 0; i < 2; i++) {
            int row = (i == 0) ? a_row0 : a_row1;
            float4 v = r[i];
            if (has_bn) {
                int kidx = k0 + a_c4 * 4;
                float4 sc = *(const float4*)&bnp_s[kidx];
                float4 sh = *(const float4*)&bnp_s[K + kidx];
                v.x = fmaxf(fmaf(v.x, sc.x, sh.x), 0.f);
                v.y = fmaxf(fmaf(v.y, sc.y, sh.y), 0.f);
                v.z = fmaxf(fmaf(v.z, sc.z, sh.z), 0.f);
                v.w = fmaxf(fmaf(v.w, sc.w, sh.w), 0.f);
            }
            float f[4] = {v.x, v.y, v.z, v.w};
            __half h[4], l[4];
#pragma unroll
            for (int q = 0; q < 4; q++) {
                h[q] = __float2half_rn(f[q]);
                l[q] = __float2half_rn(f[q] - __half2float(h[q]));
            }
            uint2 uh, ul;
            ((__half2*)&uh)[0] = __halves2half2(h[0], h[1]);
            ((__half2*)&uh)[1] = __halves2half2(h[2], h[3]);
            ((__half2*)&ul)[0] = __halves2half2(l[0], l[1]);
            ((__half2*)&ul)[1] = __halves2half2(l[2], l[3]);
            *(uint2*)&Ah[s][row][a_c4 * 4] = uh;
            *(uint2*)&Al[s][row][a_c4 * 4] = ul;
        }
    };
    auto ldB = [&](int k0, int s) {
#pragma unroll
        for (int i = 0; i < (BCH + 255) / 256; i++) {
            int idx = tid + i * 256;
            if (BCH >= 256 || idx < BCH) {
                int n  = idx >> 2;
                int c8 = idx & 3;
                uint32_t dst = bh_base[s] + (uint32_t)(n * LDA + c8 * 8) * 2;
                cp_async16(dst, Wh + (size_t)n * K + k0 + c8 * 8);
            }
        }
        cp_commit();
    };

    float acc[MT][NT][4];
#pragma unroll
    for (int mt = 0; mt < MT; mt++)
#pragma unroll
        for (int nt = 0; nt < NT; nt++)
#pragma unroll
            for (int q = 0; q < 4; q++) acc[mt][nt][q] = 0.0f;

    // Pipeline prologue: stage tile 0 into buffer 0
    float4 cur[2];
    ldA(0, cur);
    ldB(0, 0);
    stA(cur, 0, 0);
    cp_wait0();
    __syncthreads();

    int c = 0;
    for (int k0 = 0; k0 < K; k0 += BK) {
        const int n = c ^ 1;
        const bool more = (k0 + BK < K);
        float4 nxt[2];
        if (more) {
            ldB(k0 + BK, n);        // cp.async in flight through compute
            ldA(k0 + BK, nxt);      // LDGs in flight through compute
        }

#pragma unroll
        for (int kk = 0; kk < BK; kk += 16) {
            uint32_t ah[MT][4], al[MT][4], bh[NT][2];
#pragma unroll
            for (int mt = 0; mt < MT; mt++) {
                uint32_t off = (uint32_t)((wmi * 32 + mt * 16 + arow) * LDA + kk + acol) * 2;
                ldsm_x4(ah[mt], ah_base[c] + off);
                ldsm_x4(al[mt], al_base[c] + off);
            }
#pragma unroll
            for (int nt = 0; nt < NT; nt++) {
                uint32_t off = (uint32_t)((wni * WNW + nt * 8 + brow) * LDA + kk + bcol) * 2;
                ldsm_x2(bh[nt], bh_base[c] + off);
            }
#pragma unroll
            for (int mt = 0; mt < MT; mt++)
#pragma unroll
                for (int nt = 0; nt < NT; nt++) {
                    mma16816(acc[mt][nt], ah[mt], bh[nt]);
                    mma16816(acc[mt][nt], al[mt], bh[nt]);
                }
        }

        if (more) {
            stA(nxt, k0 + BK, n);
            cp_wait0();
        }
        __syncthreads();
        c = n;
    }

    // ---- epilogue: scale by dis, convert to fp16, store ----
#pragma unroll
    for (int mt = 0; mt < MT; mt++) {
#pragma unroll
        for (int nt = 0; nt < NT; nt++) {
            int r0 = m0 + wmi * 32 + mt * 16 + g;
            int r1 = r0 + 8;
            int cc = wni * WNW + nt * 8 + t4 * 2;
            if (r0 < M) {
                float d = __ldg(disv + r0);
                *(__half2*)&C16[(size_t)r0 * BN + cc] =
                    __floats2half2_rn(acc[mt][nt][0] * d, acc[mt][nt][1] * d);
            }
            if (r1 < M) {
                float d = __ldg(disv + r1);
                *(__half2*)&C16[(size_t)r1 * BN + cc] =
                    __floats2half2_rn(acc[mt][nt][2] * d, acc[mt][nt][3] * d);
            }
        }
    }
}

template <int BN>
__global__ __launch_bounds__(256) void k_mma_gemm(
    const float* __restrict__ A, const __half* __restrict__ Wh,
    __half* __restrict__ C16, const float* __restrict__ disv, int M, int K,
    const float* __restrict__ stats, const float* __restrict__ gam,
    const float* __restrict__ bt)
{
    gemm_body<BN>(blockIdx.x, A, Wh, C16, disv, M, K, stats, gam, bt);
}

// Fused CSR scatter + layer-1 GEMM (independent work, interleaved block stripe)
__global__ __launch_bounds__(256) void k_scatter_gemm1(
    const int* __restrict__ ei, int* __restrict__ cursor, int* __restrict__ csr_src,
    int E, int ngemm,
    const float* __restrict__ A, const __half* __restrict__ Wh,
    __half* __restrict__ C16, const float* __restrict__ disv, int M)
{
    int b = blockIdx.x;
    bool is_gemm;
    int id;
    if (b < 2 * ngemm) { is_gemm = (b & 1); id = b >> 1; }
    else               { is_gemm = false;   id = b - ngemm; }
    if (!is_gemm) {
        int e = id * 256 + threadIdx.x;
        if (e < E) {
            int src = __ldg(ei + e);
            int dst = __ldg(ei + E + e);
            int pos = atomicAdd(&cursor[dst], 1);
            csr_src[pos] = src;
        }
        return;
    }
    gemm_body<128>(id, A, Wh, C16, disv, M, 256, nullptr, nullptr, nullptr);
}

// ---------------------------------------------------------------------------
// CSR gather on fp16 prescaled rows + fused BN statistics (8-edge unroll).
// Output agg is fp32.
// ---------------------------------------------------------------------------
template <int F>
__global__ __launch_bounds__(256) void k_gather16(
    const int* __restrict__ rowptr, const int* __restrict__ deg,
    const int* __restrict__ csr_src, const __half* __restrict__ h16,
    const float* __restrict__ dis, const float* __restrict__ bias,
    float* __restrict__ agg, float* __restrict__ stats, int N)
{
    constexpr int G = F / 8;
    __shared__ float ssum[F];
    __shared__ float ssq[F];
    const int tid = threadIdx.x;
    if (tid < F) { ssum[tid] = 0.0f; ssq[tid] = 0.0f; }
    __syncthreads();

    int t    = blockIdx.x * 256 + tid;
    int node = t / G;
    int j    = t - node * G;
    const bool valid = node < N;
    const int cn = valid ? node : 0;

    int start = __ldg(rowptr + cn);
    int cnt   = valid ? __ldg(deg + cn) : 0;
    const __half* base = h16 + j * 8;

    float a[8];
#pragma unroll
    for (int q = 0; q < 8; q++) a[q] = 0.0f;

    auto addv = [&](uint4 v) {
        const __half2* hv = (const __half2*)&v;
#pragma unroll
        for (int q = 0; q < 4; q++) {
            float2 f = __half22float2(hv[q]);
            a[2 * q]     += f.x;
            a[2 * q + 1] += f.y;
        }
    };

    int p = 0;
    for (; p + 8 <= cnt; p += 8) {
        int s[8];
#pragma unroll
        for (int u = 0; u < 8; u++) s[u] = __ldg(csr_src + start + p + u);
        uint4 v[8];
#pragma unroll
        for (int u = 0; u < 8; u++) v[u] = __ldg((const uint4*)(base + (size_t)s[u] * F));
#pragma unroll
        for (int u = 0; u < 8; u++) addv(v[u]);
    }
    for (; p + 4 <= cnt; p += 4) {
        int s0 = __ldg(csr_src + start + p);
        int s1 = __ldg(csr_src + start + p + 1);
        int s2 = __ldg(csr_src + start + p + 2);
        int s3 = __ldg(csr_src + start + p + 3);
        uint4 v0 = __ldg((const uint4*)(base + (size_t)s0 * F));
        uint4 v1 = __ldg((const uint4*)(base + (size_t)s1 * F));
        uint4 v2 = __ldg((const uint4*)(base + (size_t)s2 * F));
        uint4 v3 = __ldg((const uint4*)(base + (size_t)s3 * F));
        addv(v0); addv(v1); addv(v2); addv(v3);
    }
    for (; p < cnt; p++) {
        int s = __ldg(csr_src + start + p);
        addv(__ldg((const uint4*)(base + (size_t)s * F)));
    }
    if (valid) addv(__ldg((const uint4*)(base + (size_t)cn * F)));  // self-loop

    float d = valid ? __ldg(dis + cn) : 0.0f;
    float4 b0 = __ldg((const float4*)(bias + j * 8));
    float4 b1 = __ldg((const float4*)(bias + j * 8) + 1);
    float r[8];
    r[0] = fmaf(d, a[0], b0.x); r[1] = fmaf(d, a[1], b0.y);
    r[2] = fmaf(d, a[2], b0.z); r[3] = fmaf(d, a[3], b0.w);
    r[4] = fmaf(d, a[4], b1.x); r[5] = fmaf(d, a[5], b1.y);
    r[6] = fmaf(d, a[6], b1.z); r[7] = fmaf(d, a[7], b1.w);

    if (valid) {
        float4* o = (float4*)(agg + (size_t)node * F + j * 8);
        o[0] = make_float4(r[0], r[1], r[2], r[3]);
        o[1] = make_float4(r[4], r[5], r[6], r[7]);
    } else {
#pragma unroll
        for (int q = 0; q < 8; q++) r[q] = 0.0f;
    }

    float s2v[8];
#pragma unroll
    for (int q = 0; q < 8; q++) s2v[q] = r[q] * r[q];
#pragma unroll
    for (int o = 16; o >= G; o >>= 1) {
#pragma unroll
        for (int q = 0; q < 8; q++) {
            r[q]   += __shfl_xor_sync(0xFFFFFFFFu, r[q],   o);
            s2v[q] += __shfl_xor_sync(0xFFFFFFFFu, s2v[q], o);
        }
    }
    int lane = tid & 31;
    if (lane < G) {
#pragma unroll
        for (int q = 0; q < 8; q++) {
            atomicAdd(&ssum[lane * 8 + q], r[q]);
            atomicAdd(&ssq[lane * 8 + q],  s2v[q]);
        }
    }
    __syncthreads();
    if (tid < F) {
        atomicAdd(&stats[tid],     ssum[tid]);
        atomicAdd(&stats[F + tid], ssq[tid]);
    }
}

// ---------------------------------------------------------------------------
// Final FC with in-kernel BN finalize + fused BN+ReLU (fp32 input)
// ---------------------------------------------------------------------------
__global__ void k_final_fc(const float* __restrict__ h, const float* __restrict__ stats,
                           const float* __restrict__ gam, const float* __restrict__ bt,
                           const float* __restrict__ W, const float* __restrict__ b,
                           float* __restrict__ out, int N)
{
    __shared__ float sc_s[32], sh_s[32];
    int tid = threadIdx.x;
    if (tid < 32) {
        float inv_n = 1.0f / (float)N;
        float mu  = stats[tid] * inv_n;
        float var = fmaxf(stats[32 + tid] * inv_n - mu * mu, 0.0f);
        float sc  = gam[tid] * rsqrtf(var + 1e-5f);
        sc_s[tid] = sc;
        sh_s[tid] = bt[tid] - mu * sc;
    }
    __syncthreads();
    int lane = tid & 31;
    int node = (blockIdx.x * blockDim.x + tid) >> 5;
    if (node >= N) return;
    float v = fmaxf(fmaf(h[(size_t)node * 32 + lane], sc_s[lane], sh_s[lane]), 0.0f)
              * __ldg(W + lane);
#pragma unroll
    for (int o = 16; o; o >>= 1) v += __shfl_down_sync(0xFFFFFFFFu, v, o);
    if (lane == 0) out[node] = v + __ldg(b);
}

// ---------------------------------------------------------------------------
static inline int cdiv(long long a, long long b) { return (int)((a + b - 1) / b); }

extern "C" void kernel_launch(void* const* d_in, const int* in_sizes, int n_in,
                              void* d_out, int out_size)
{
    const float* x   = (const float*)d_in[0];
    const int*   ei  = (const int*)d_in[1];
    const float* W1  = (const float*)d_in[2];
    const float* b1  = (const float*)d_in[3];
    const float* g1  = (const float*)d_in[4];
    const float* bt1 = (const float*)d_in[5];
    const float* W2  = (const float*)d_in[6];
    const float* b2  = (const float*)d_in[7];
    const float* g2  = (const float*)d_in[8];
    const float* bt2 = (const float*)d_in[9];
    const float* W3  = (const float*)d_in[10];
    const float* b3  = (const float*)d_in[11];
    const float* g3  = (const float*)d_in[12];
    const float* bt3 = (const float*)d_in[13];
    const float* Wfc = (const float*)d_in[14];
    const float* bfc = (const float*)d_in[15];
    float* out = (float*)d_out;

    const int N = in_sizes[0] / 256;
    const int E = in_sizes[1] / 2;

    float *agg, *dis, *stats;
    __half *h16, *whi;
    int *deg, *rowptr, *cursor, *bsum, *csr;
    cudaGetSymbolAddress((void**)&agg,    g_agg);
    cudaGetSymbolAddress((void**)&h16,    g_h16);
    cudaGetSymbolAddress((void**)&dis,    g_dis);
    cudaGetSymbolAddress((void**)&deg,    g_deg);
    cudaGetSymbolAddress((void**)&rowptr, g_rowptr);
    cudaGetSymbolAddress((void**)&cursor, g_cursor);
    cudaGetSymbolAddress((void**)&bsum,   g_bsum);
    cudaGetSymbolAddress((void**)&csr,    g_csr_src);
    cudaGetSymbolAddress((void**)&stats,  g_stats);
    cudaGetSymbolAddress((void**)&whi,    g_whi);

    const int nsc   = cdiv(E, 256);
    const int nw    = cdiv(WTOT, 256);
    const int nb    = cdiv(N, 1024);
    const int ngemm = cdiv(N, 64);

    // ---- prologue: degree count + weight round, scan(+dis), scatter+GEMM1 ----
    cudaMemsetAsync(deg, 0, (size_t)N * sizeof(int));
    k_pro1<<<nsc + nw, 256>>>(ei, deg, E, nsc, W1, W2, W3, whi);
    k_scan_block<<<nb, 1024>>>(deg, rowptr, bsum, dis, N);
    k_scan_add2<<<cdiv(N, 256), 256>>>(rowptr, cursor, bsum, stats, nb, N);
    k_scatter_gemm1<<<ngemm + nsc, 256>>>(ei, cursor, csr, E, ngemm,
                                          x, whi, h16, dis, N);

    // ================= Layer 1 gather (F=128) =================
    k_gather16<128><<<cdiv((long long)N * 16, 256), 256>>>(
        rowptr, deg, csr, h16, dis, b1, agg, stats, N);

    // ================= Layer 2: 128 -> 64 =================
    k_mma_gemm<64><<<ngemm, 256>>>(agg, whi + W2_OFF, h16, dis, N, 128,
                                   stats, g1, bt1);
    k_gather16<64><<<cdiv((long long)N * 8, 256), 256>>>(
        rowptr, deg, csr, h16, dis, b2, agg, stats + ST2, N);

    // ================= Layer 3: 64 -> 32 =================
    k_mma_gemm<32><<<ngemm, 256>>>(agg, whi + W3_OFF, h16, dis, N, 64,
                                   stats + ST2, g2, bt2);
    k_gather16<32><<<cdiv((long long)N * 4, 256), 256>>>(
        rowptr, deg, csr, h16, dis, b3, agg, stats + ST3, N);

    // ================= Final FC: 32 -> 1 (in-kernel BN + ReLU) =================
    k_final_fc<<<cdiv((long long)N * 32, 256), 256>>>(agg, stats + ST3, g3, bt3,
                                                      Wfc, bfc, out, N);
}

// round 14
// speedup vs baseline: 1.0456x; 1.0456x over previous
#include <cuda_runtime.h>
#include <cuda_fp16.h>
#include <cuda_bf16.h>
#include <cstdint>

#define MAXN 100000
#define MAXE 3200000
#define MAXF 128

#define W2_OFF (256 * 128)
#define W3_OFF (256 * 128 + 128 * 64)
#define WTOT   (256 * 128 + 128 * 64 + 64 * 32)

// stats regions: [0,256) layer1 (F=128), [256,384) layer2 (F=64), [384,448) layer3 (F=32)
#define ST2 256
#define ST3 384
#define STTOT 448

// Scratch (device globals; no cudaMalloc allowed)
__device__ float  g_agg[(size_t)MAXN * MAXF];        // fp32 aggregation output
__device__ __half g_h16[(size_t)MAXN * MAXF];        // fp16 dis-prescaled features
__device__ float  g_dis[MAXN];
__device__ int    g_deg[MAXN];
__device__ int    g_rowptr[MAXN + 1];
__device__ int    g_cursor[MAXN + 1];
__device__ int    g_bsum[256];
__device__ int    g_csr_src[MAXE];
__device__ float  g_stats[STTOT];
__device__ __half g_whi[WTOT];

// ---------------------------------------------------------------------------
// Prologue 1: fused degree count + weight fp16 round/transpose
// ---------------------------------------------------------------------------
__global__ void k_pro1(const int* __restrict__ ei, int* __restrict__ deg, int E, int nsc,
                       const float* __restrict__ W1, const float* __restrict__ W2,
                       const float* __restrict__ W3, __half* __restrict__ Wh)
{
    if ((int)blockIdx.x < nsc) {
        int e = blockIdx.x * 256 + threadIdx.x;
        if (e < E) atomicAdd(&deg[__ldg(ei + E + e)], 1);
        return;
    }
    int i = (blockIdx.x - nsc) * 256 + threadIdx.x;
    const float* W;
    int K, Nn, off, li;
    if (i < W2_OFF)       { W = W1; K = 256; Nn = 128; off = 0;      li = i; }
    else if (i < W3_OFF)  { W = W2; K = 128; Nn = 64;  off = W2_OFF; li = i - W2_OFF; }
    else if (i < WTOT)    { W = W3; K = 64;  Nn = 32;  off = W3_OFF; li = i - W3_OFF; }
    else return;
    int n = li / K, k = li - n * K;
    Wh[off + li] = __float2half_rn(__ldg(W + (size_t)k * Nn + n));
}

// ---------------------------------------------------------------------------
// Scan (exclusive) of deg -> rowptr; also emits dis = rsqrt(deg+1)
// ---------------------------------------------------------------------------
__global__ void k_scan_block(const int* __restrict__ deg, int* __restrict__ exc,
                             int* __restrict__ bsum, float* __restrict__ dis, int N)
{
    __shared__ int sh[1024];
    int i = blockIdx.x * 1024 + threadIdx.x;
    int v = (i < N) ? deg[i] : 0;
    sh[threadIdx.x] = v;
    __syncthreads();
#pragma unroll
    for (int o = 1; o < 1024; o <<= 1) {
        int t = (threadIdx.x >= o) ? sh[threadIdx.x - o] : 0;
        __syncthreads();
        sh[threadIdx.x] += t;
        __syncthreads();
    }
    if (i < N) {
        exc[i] = sh[threadIdx.x] - v;
        dis[i] = rsqrtf((float)v + 1.0f);
    }
    if (threadIdx.x == 1023) bsum[blockIdx.x] = sh[1023];
}

// Adds block offsets (bsum scanned redundantly per block in smem),
// mirrors rowptr->cursor, zeroes ALL BN stats regions.
__global__ void k_scan_add2(int* __restrict__ rowptr, int* __restrict__ cursor,
                            const int* __restrict__ bsum, float* __restrict__ stats,
                            int nb, int N)
{
    __shared__ int sh[256];
    __shared__ int sexc[256];
    int t = threadIdx.x;
    int v = (t < nb) ? __ldg(bsum + t) : 0;
    sh[t] = v;
    __syncthreads();
#pragma unroll
    for (int o = 1; o < 256; o <<= 1) {
        int u = (t >= o) ? sh[t - o] : 0;
        __syncthreads();
        sh[t] += u;
        __syncthreads();
    }
    sexc[t] = sh[t] - v;   // exclusive prefix of bsum
    __syncthreads();

    int i = blockIdx.x * 256 + t;
    if (i < N) {
        int val = rowptr[i] + sexc[i >> 10];
        rowptr[i] = val;
        cursor[i] = val;
    }
    if (blockIdx.x == 0) {
        for (int f = t; f < STTOT; f += 256) stats[f] = 0.0f;
    }
}

// ---------------------------------------------------------------------------
// MMA + ldmatrix helpers
// ---------------------------------------------------------------------------
__device__ __forceinline__ void mma16816(float* c, const uint32_t* a, const uint32_t* b)
{
    asm volatile(
        "mma.sync.aligned.m16n8k16.row.col.f32.f16.f16.f32 "
        "{%0,%1,%2,%3}, {%4,%5,%6,%7}, {%8,%9}, {%0,%1,%2,%3};"
        : "+f"(c[0]), "+f"(c[1]), "+f"(c[2]), "+f"(c[3])
        : "r"(a[0]), "r"(a[1]), "r"(a[2]), "r"(a[3]), "r"(b[0]), "r"(b[1]));
}
__device__ __forceinline__ void ldsm_x4(uint32_t* r, uint32_t addr)
{
    asm volatile("ldmatrix.sync.aligned.m8n8.x4.shared.b16 {%0,%1,%2,%3}, [%4];"
                 : "=r"(r[0]), "=r"(r[1]), "=r"(r[2]), "=r"(r[3]) : "r"(addr));
}
__device__ __forceinline__ void ldsm_x2(uint32_t* r, uint32_t addr)
{
    asm volatile("ldmatrix.sync.aligned.m8n8.x2.shared.b16 {%0,%1}, [%2];"
                 : "=r"(r[0]), "=r"(r[1]) : "r"(addr));
}

// ---------------------------------------------------------------------------
// 2-product split GEMM core (A fp32, hi/lo split; W fp16-rounded),
// ldmatrix fragment loads, register-pipelined A global loads:
//   C16[M,BN] = half( dis[m] * (BNReLU?(A[M,K]) @ W16[K,BN]) )
// BN scale/shift computed in-kernel from raw stats (if stats != nullptr).
// BM=64, BK=32, 256 threads (8 warps 2x4), warp tile 32 x (BN/4).
// __launch_bounds__(256, 4) on callers caps regs at 64 -> 4 blocks/SM.
// ---------------------------------------------------------------------------
template <int BN>
__device__ __forceinline__ void gemm_body(
    int bid, const float* __restrict__ A, const __half* __restrict__ Wh,
    __half* __restrict__ C16, const float* __restrict__ disv, int M, int K,
    const float* __restrict__ stats, const float* __restrict__ gam,
    const float* __restrict__ bt)
{
    constexpr int BM = 64, BK = 32;
    constexpr int LDA = BK + 8;           // halfs; 80B row stride
    constexpr int MT = 2;
    constexpr int NT = BN / 32;
    constexpr int WNW = BN / 4;

    __shared__ __align__(16) __half Ah[BM][LDA];
    __shared__ __align__(16) __half Al[BM][LDA];
    __shared__ __align__(16) __half Bh[BN][LDA];
    __shared__ __align__(16) float bnp_s[512];   // [K] scale | [K] shift

    const int tid  = threadIdx.x;
    const int warp = tid >> 5;
    const int lane = tid & 31;
    const int g    = lane >> 2;
    const int t4   = lane & 3;
    const int wmi  = warp & 1;
    const int wni  = warp >> 1;
    const int m0   = bid * BM;
    const bool has_bn = (stats != nullptr);

    const uint32_t ah_base = (uint32_t)__cvta_generic_to_shared(&Ah[0][0]);
    const uint32_t al_base = (uint32_t)__cvta_generic_to_shared(&Al[0][0]);
    const uint32_t bh_base = (uint32_t)__cvta_generic_to_shared(&Bh[0][0]);
    const int arow = lane & 15;
    const int acol = (lane & 16) ? 8 : 0;
    const int brow = lane & 7;
    const int bcol = (lane & 8) ? 8 : 0;

    if (has_bn) {
        float inv_n = 1.0f / (float)M;
        for (int f = tid; f < K; f += 256) {
            float mu  = stats[f] * inv_n;
            float var = fmaxf(stats[K + f] * inv_n - mu * mu, 0.0f);
            float sc  = gam[f] * rsqrtf(var + 1e-5f);
            bnp_s[f]     = sc;
            bnp_s[K + f] = bt[f] - mu * sc;
        }
    }
    __syncthreads();

    // A staging: 64x32 floats = 512 float4, 2 per thread
    const int a_row0 = tid >> 3;
    const int a_row1 = (tid + 256) >> 3;
    const int a_c4   = tid & 7;

    auto ldA = [&](int k0, float4* r) {
        int gr0 = m0 + a_row0;
        int gr1 = m0 + a_row1;
        r[0] = (gr0 < M) ? *(const float4*)(A + (size_t)gr0 * K + k0 + a_c4 * 4)
                         : make_float4(0.f, 0.f, 0.f, 0.f);
        r[1] = (gr1 < M) ? *(const float4*)(A + (size_t)gr1 * K + k0 + a_c4 * 4)
                         : make_float4(0.f, 0.f, 0.f, 0.f);
    };

    auto stA = [&](float4* r, int k0) {
#pragma unroll
        for (int i = 0; i < 2; i++) {
            int row = (i == 0) ? a_row0 : a_row1;
            float4 v = r[i];
            if (has_bn) {
                int kidx = k0 + a_c4 * 4;
                float4 sc = *(const float4*)&bnp_s[kidx];
                float4 sh = *(const float4*)&bnp_s[K + kidx];
                v.x = fmaxf(fmaf(v.x, sc.x, sh.x), 0.f);
                v.y = fmaxf(fmaf(v.y, sc.y, sh.y), 0.f);
                v.z = fmaxf(fmaf(v.z, sc.z, sh.z), 0.f);
                v.w = fmaxf(fmaf(v.w, sc.w, sh.w), 0.f);
            }
            float f[4] = {v.x, v.y, v.z, v.w};
            __half h[4], l[4];
#pragma unroll
            for (int q = 0; q < 4; q++) {
                h[q] = __float2half_rn(f[q]);
                l[q] = __float2half_rn(f[q] - __half2float(h[q]));
            }
            uint2 uh, ul;
            ((__half2*)&uh)[0] = __halves2half2(h[0], h[1]);
            ((__half2*)&uh)[1] = __halves2half2(h[2], h[3]);
            ((__half2*)&ul)[0] = __halves2half2(l[0], l[1]);
            ((__half2*)&ul)[1] = __halves2half2(l[2], l[3]);
            *(uint2*)&Ah[row][a_c4 * 4] = uh;
            *(uint2*)&Al[row][a_c4 * 4] = ul;
        }
    };

    float acc[MT][NT][4];
#pragma unroll
    for (int mt = 0; mt < MT; mt++)
#pragma unroll
        for (int nt = 0; nt < NT; nt++)
#pragma unroll
            for (int q = 0; q < 4; q++) acc[mt][nt][q] = 0.0f;

    float4 cur[2];
    ldA(0, cur);

    for (int k0 = 0; k0 < K; k0 += BK) {
        stA(cur, k0);
        // ---- stage B tile (fp16, transposed [BN][K]; L2-resident) ----
#pragma unroll
        for (int i = 0; i < (BN * 4 + 255) / 256; i++) {
            int idx = tid + i * 256;
            if (idx < BN * 4) {
                int n  = idx >> 2;
                int c8 = idx & 3;
                *(uint4*)&Bh[n][c8 * 8] = *(const uint4*)(Wh + (size_t)n * K + k0 + c8 * 8);
            }
        }
        __syncthreads();

        // ---- prefetch next A tile into registers (LDGs overlap compute) ----
        float4 nxt[2];
        if (k0 + BK < K) ldA(k0 + BK, nxt);
        else { nxt[0] = make_float4(0.f,0.f,0.f,0.f); nxt[1] = nxt[0]; }

#pragma unroll
        for (int kk = 0; kk < BK; kk += 16) {
            uint32_t ah[MT][4], al[MT][4], bh[NT][2];
#pragma unroll
            for (int mt = 0; mt < MT; mt++) {
                uint32_t off = ((wmi * 32 + mt * 16 + arow) * LDA + kk + acol) * 2;
                ldsm_x4(ah[mt], ah_base + off);
                ldsm_x4(al[mt], al_base + off);
            }
#pragma unroll
            for (int nt = 0; nt < NT; nt++) {
                uint32_t off = ((wni * WNW + nt * 8 + brow) * LDA + kk + bcol) * 2;
                ldsm_x2(bh[nt], bh_base + off);
            }
#pragma unroll
            for (int mt = 0; mt < MT; mt++)
#pragma unroll
                for (int nt = 0; nt < NT; nt++) {
                    mma16816(acc[mt][nt], ah[mt], bh[nt]);
                    mma16816(acc[mt][nt], al[mt], bh[nt]);
                }
        }
        __syncthreads();
        cur[0] = nxt[0];
        cur[1] = nxt[1];
    }

    // ---- epilogue: scale by dis, convert to fp16, store ----
#pragma unroll
    for (int mt = 0; mt < MT; mt++) {
#pragma unroll
        for (int nt = 0; nt < NT; nt++) {
            int r0 = m0 + wmi * 32 + mt * 16 + g;
            int r1 = r0 + 8;
            int c  = wni * WNW + nt * 8 + t4 * 2;
            if (r0 < M) {
                float d = __ldg(disv + r0);
                *(__half2*)&C16[(size_t)r0 * BN + c] =
                    __floats2half2_rn(acc[mt][nt][0] * d, acc[mt][nt][1] * d);
            }
            if (r1 < M) {
                float d = __ldg(disv + r1);
                *(__half2*)&C16[(size_t)r1 * BN + c] =
                    __floats2half2_rn(acc[mt][nt][2] * d, acc[mt][nt][3] * d);
            }
        }
    }
}

template <int BN>
__global__ __launch_bounds__(256, 4) void k_mma_gemm(
    const float* __restrict__ A, const __half* __restrict__ Wh,
    __half* __restrict__ C16, const float* __restrict__ disv, int M, int K,
    const float* __restrict__ stats, const float* __restrict__ gam,
    const float* __restrict__ bt)
{
    gemm_body<BN>(blockIdx.x, A, Wh, C16, disv, M, K, stats, gam, bt);
}

// Fused CSR scatter + layer-1 GEMM (independent work, interleaved block stripe)
__global__ __launch_bounds__(256, 4) void k_scatter_gemm1(
    const int* __restrict__ ei, int* __restrict__ cursor, int* __restrict__ csr_src,
    int E, int ngemm,
    const float* __restrict__ A, const __half* __restrict__ Wh,
    __half* __restrict__ C16, const float* __restrict__ disv, int M)
{
    int b = blockIdx.x;
    bool is_gemm;
    int id;
    if (b < 2 * ngemm) { is_gemm = (b & 1); id = b >> 1; }
    else               { is_gemm = false;   id = b - ngemm; }
    if (!is_gemm) {
        int e = id * 256 + threadIdx.x;
        if (e < E) {
            int src = __ldg(ei + e);
            int dst = __ldg(ei + E + e);
            int pos = atomicAdd(&cursor[dst], 1);
            csr_src[pos] = src;
        }
        return;
    }
    gemm_body<128>(id, A, Wh, C16, disv, M, 256, nullptr, nullptr, nullptr);
}

// ---------------------------------------------------------------------------
// CSR gather on fp16 prescaled rows + fused BN statistics (4-edge unroll).
// Output agg is fp32.
// ---------------------------------------------------------------------------
template <int F>
__global__ __launch_bounds__(256) void k_gather16(
    const int* __restrict__ rowptr, const int* __restrict__ deg,
    const int* __restrict__ csr_src, const __half* __restrict__ h16,
    const float* __restrict__ dis, const float* __restrict__ bias,
    float* __restrict__ agg, float* __restrict__ stats, int N)
{
    constexpr int G = F / 8;
    __shared__ float ssum[F];
    __shared__ float ssq[F];
    const int tid = threadIdx.x;
    if (tid < F) { ssum[tid] = 0.0f; ssq[tid] = 0.0f; }
    __syncthreads();

    int t    = blockIdx.x * 256 + tid;
    int node = t / G;
    int j    = t - node * G;
    const bool valid = node < N;
    const int cn = valid ? node : 0;

    int start = __ldg(rowptr + cn);
    int cnt   = valid ? __ldg(deg + cn) : 0;
    const __half* base = h16 + j * 8;

    float a[8];
#pragma unroll
    for (int q = 0; q < 8; q++) a[q] = 0.0f;

    auto addv = [&](uint4 v) {
        const __half2* hv = (const __half2*)&v;
#pragma unroll
        for (int q = 0; q < 4; q++) {
            float2 f = __half22float2(hv[q]);
            a[2 * q]     += f.x;
            a[2 * q + 1] += f.y;
        }
    };

    int p = 0;
    for (; p + 4 <= cnt; p += 4) {
        int s0 = __ldg(csr_src + start + p);
        int s1 = __ldg(csr_src + start + p + 1);
        int s2 = __ldg(csr_src + start + p + 2);
        int s3 = __ldg(csr_src + start + p + 3);
        uint4 v0 = __ldg((const uint4*)(base + (size_t)s0 * F));
        uint4 v1 = __ldg((const uint4*)(base + (size_t)s1 * F));
        uint4 v2 = __ldg((const uint4*)(base + (size_t)s2 * F));
        uint4 v3 = __ldg((const uint4*)(base + (size_t)s3 * F));
        addv(v0); addv(v1); addv(v2); addv(v3);
    }
    for (; p < cnt; p++) {
        int s = __ldg(csr_src + start + p);
        addv(__ldg((const uint4*)(base + (size_t)s * F)));
    }
    if (valid) addv(__ldg((const uint4*)(base + (size_t)cn * F)));  // self-loop

    float d = valid ? __ldg(dis + cn) : 0.0f;
    float4 b0 = __ldg((const float4*)(bias + j * 8));
    float4 b1 = __ldg((const float4*)(bias + j * 8) + 1);
    float r[8];
    r[0] = fmaf(d, a[0], b0.x); r[1] = fmaf(d, a[1], b0.y);
    r[2] = fmaf(d, a[2], b0.z); r[3] = fmaf(d, a[3], b0.w);
    r[4] = fmaf(d, a[4], b1.x); r[5] = fmaf(d, a[5], b1.y);
    r[6] = fmaf(d, a[6], b1.z); r[7] = fmaf(d, a[7], b1.w);

    if (valid) {
        float4* o = (float4*)(agg + (size_t)node * F + j * 8);
        o[0] = make_float4(r[0], r[1], r[2], r[3]);
        o[1] = make_float4(r[4], r[5], r[6], r[7]);
    } else {
#pragma unroll
        for (int q = 0; q < 8; q++) r[q] = 0.0f;
    }

    float s2v[8];
#pragma unroll
    for (int q = 0; q < 8; q++) s2v[q] = r[q] * r[q];
#pragma unroll
    for (int o = 16; o >= G; o >>= 1) {
#pragma unroll
        for (int q = 0; q < 8; q++) {
            r[q]   += __shfl_xor_sync(0xFFFFFFFFu, r[q],   o);
            s2v[q] += __shfl_xor_sync(0xFFFFFFFFu, s2v[q], o);
        }
    }
    int lane = tid & 31;
    if (lane < G) {
#pragma unroll
        for (int q = 0; q < 8; q++) {
            atomicAdd(&ssum[lane * 8 + q], r[q]);
            atomicAdd(&ssq[lane * 8 + q],  s2v[q]);
        }
    }
    __syncthreads();
    if (tid < F) {
        atomicAdd(&stats[tid],     ssum[tid]);
        atomicAdd(&stats[F + tid], ssq[tid]);
    }
}

// ---------------------------------------------------------------------------
// Final FC with in-kernel BN finalize + fused BN+ReLU (fp32 input)
// ---------------------------------------------------------------------------
__global__ void k_final_fc(const float* __restrict__ h, const float* __restrict__ stats,
                           const float* __restrict__ gam, const float* __restrict__ bt,
                           const float* __restrict__ W, const float* __restrict__ b,
                           float* __restrict__ out, int N)
{
    __shared__ float sc_s[32], sh_s[32];
    int tid = threadIdx.x;
    if (tid < 32) {
        float inv_n = 1.0f / (float)N;
        float mu  = stats[tid] * inv_n;
        float var = fmaxf(stats[32 + tid] * inv_n - mu * mu, 0.0f);
        float sc  = gam[tid] * rsqrtf(var + 1e-5f);
        sc_s[tid] = sc;
        sh_s[tid] = bt[tid] - mu * sc;
    }
    __syncthreads();
    int lane = tid & 31;
    int node = (blockIdx.x * blockDim.x + tid) >> 5;
    if (node >= N) return;
    float v = fmaxf(fmaf(h[(size_t)node * 32 + lane], sc_s[lane], sh_s[lane]), 0.0f)
              * __ldg(W + lane);
#pragma unroll
    for (int o = 16; o; o >>= 1) v += __shfl_down_sync(0xFFFFFFFFu, v, o);
    if (lane == 0) out[node] = v + __ldg(b);
}

// ---------------------------------------------------------------------------
static inline int cdiv(long long a, long long b) { return (int)((a + b - 1) / b); }

extern "C" void kernel_launch(void* const* d_in, const int* in_sizes, int n_in,
                              void* d_out, int out_size)
{
    const float* x   = (const float*)d_in[0];
    const int*   ei  = (const int*)d_in[1];
    const float* W1  = (const float*)d_in[2];
    const float* b1  = (const float*)d_in[3];
    const float* g1  = (const float*)d_in[4];
    const float* bt1 = (const float*)d_in[5];
    const float* W2  = (const float*)d_in[6];
    const float* b2  = (const float*)d_in[7];
    const float* g2  = (const float*)d_in[8];
    const float* bt2 = (const float*)d_in[9];
    const float* W3  = (const float*)d_in[10];
    const float* b3  = (const float*)d_in[11];
    const float* g3  = (const float*)d_in[12];
    const float* bt3 = (const float*)d_in[13];
    const float* Wfc = (const float*)d_in[14];
    const float* bfc = (const float*)d_in[15];
    float* out = (float*)d_out;

    const int N = in_sizes[0] / 256;
    const int E = in_sizes[1] / 2;

    float *agg, *dis, *stats;
    __half *h16, *whi;
    int *deg, *rowptr, *cursor, *bsum, *csr;
    cudaGetSymbolAddress((void**)&agg,    g_agg);
    cudaGetSymbolAddress((void**)&h16,    g_h16);
    cudaGetSymbolAddress((void**)&dis,    g_dis);
    cudaGetSymbolAddress((void**)&deg,    g_deg);
    cudaGetSymbolAddress((void**)&rowptr, g_rowptr);
    cudaGetSymbolAddress((void**)&cursor, g_cursor);
    cudaGetSymbolAddress((void**)&bsum,   g_bsum);
    cudaGetSymbolAddress((void**)&csr,    g_csr_src);
    cudaGetSymbolAddress((void**)&stats,  g_stats);
    cudaGetSymbolAddress((void**)&whi,    g_whi);

    const int nsc   = cdiv(E, 256);
    const int nw    = cdiv(WTOT, 256);
    const int nb    = cdiv(N, 1024);
    const int ngemm = cdiv(N, 64);

    // ---- prologue: degree count + weight round, scan(+dis), scatter+GEMM1 ----
    cudaMemsetAsync(deg, 0, (size_t)N * sizeof(int));
    k_pro1<<<nsc + nw, 256>>>(ei, deg, E, nsc, W1, W2, W3, whi);
    k_scan_block<<<nb, 1024>>>(deg, rowptr, bsum, dis, N);
    k_scan_add2<<<cdiv(N, 256), 256>>>(rowptr, cursor, bsum, stats, nb, N);
    k_scatter_gemm1<<<ngemm + nsc, 256>>>(ei, cursor, csr, E, ngemm,
                                          x, whi, h16, dis, N);

    // ================= Layer 1 gather (F=128) =================
    k_gather16<128><<<cdiv((long long)N * 16, 256), 256>>>(
        rowptr, deg, csr, h16, dis, b1, agg, stats, N);

    // ================= Layer 2: 128 -> 64 =================
    k_mma_gemm<64><<<ngemm, 256>>>(agg, whi + W2_OFF, h16, dis, N, 128,
                                   stats, g1, bt1);
    k_gather16<64><<<cdiv((long long)N * 8, 256), 256>>>(
        rowptr, deg, csr, h16, dis, b2, agg, stats + ST2, N);

    // ================= Layer 3: 64 -> 32 =================
    k_mma_gemm<32><<<ngemm, 256>>>(agg, whi + W3_OFF, h16, dis, N, 64,
                                   stats + ST2, g2, bt2);
    k_gather16<32><<<cdiv((long long)N * 4, 256), 256>>>(
        rowptr, deg, csr, h16, dis, b3, agg, stats + ST3, N);

    // ================= Final FC: 32 -> 1 (in-kernel BN + ReLU) =================
    k_final_fc<<<cdiv((long long)N * 32, 256), 256>>>(agg, stats + ST3, g3, bt3,
                                                      Wfc, bfc, out, N);
}

// round 15
// speedup vs baseline: 1.0560x; 1.0099x over previous
#include <cuda_runtime.h>
#include <cuda_fp16.h>
#include <cuda_bf16.h>
#include <cstdint>

#define MAXN 100000
#define MAXE 3200000
#define MAXF 128

#define W2_OFF (256 * 128)
#define W3_OFF (256 * 128 + 128 * 64)
#define WTOT   (256 * 128 + 128 * 64 + 64 * 32)

// stats regions: [0,256) layer1 (F=128), [256,384) layer2 (F=64), [384,448) layer3 (F=32)
#define ST2 256
#define ST3 384
#define STTOT 448

// Scratch (device globals; no cudaMalloc allowed)
__device__ float  g_agg[(size_t)MAXN * MAXF];
__device__ __half g_h16[(size_t)MAXN * MAXF];
__device__ float  g_dis[MAXN];
__device__ int    g_deg[MAXN];
__device__ int    g_rowptr[MAXN + 1];
__device__ int    g_cursor[MAXN + 1];
__device__ int    g_bsum[256];
__device__ int    g_csr_src[MAXE];
__device__ float  g_stats[STTOT];
__device__ __half g_whi[WTOT];
__device__ unsigned g_bar;     // mega-kernel grid barrier counter (reset each launch)

// ---------------------------------------------------------------------------
// L2-only load helpers (avoid stale L1 across software grid barriers)
// ---------------------------------------------------------------------------
__device__ __forceinline__ float4 ldcg_f4(const float* p) {
    float4 v;
    asm volatile("ld.global.cg.v4.f32 {%0,%1,%2,%3}, [%4];"
                 : "=f"(v.x), "=f"(v.y), "=f"(v.z), "=f"(v.w) : "l"(p));
    return v;
}
__device__ __forceinline__ uint4 ldcg_u4(const void* p) {
    uint4 v;
    asm volatile("ld.global.cg.v4.u32 {%0,%1,%2,%3}, [%4];"
                 : "=r"(v.x), "=r"(v.y), "=r"(v.z), "=r"(v.w) : "l"(p));
    return v;
}
__device__ __forceinline__ float ldcg_f(const float* p) {
    float v;
    asm volatile("ld.global.cg.f32 %0, [%1];" : "=f"(v) : "l"(p));
    return v;
}

// ---------------------------------------------------------------------------
// Grid barrier (all blocks resident by construction; counter monotonic)
// ---------------------------------------------------------------------------
__device__ __forceinline__ void grid_barrier(unsigned target) {
    __syncthreads();
    if (threadIdx.x == 0) {
        __threadfence();
        unsigned arr = atomicAdd(&g_bar, 1u) + 1u;
        if (arr < target) {
            volatile unsigned* p = &g_bar;
            while (*p < target) __nanosleep(64);
        }
        __threadfence();
    }
    __syncthreads();
}

// ---------------------------------------------------------------------------
// Prologue 1: fused degree count + weight fp16 round/transpose
// ---------------------------------------------------------------------------
__global__ void k_pro1(const int* __restrict__ ei, int* __restrict__ deg, int E, int nsc,
                       const float* __restrict__ W1, const float* __restrict__ W2,
                       const float* __restrict__ W3, __half* __restrict__ Wh)
{
    if ((int)blockIdx.x < nsc) {
        int e = blockIdx.x * 256 + threadIdx.x;
        if (e < E) atomicAdd(&deg[__ldg(ei + E + e)], 1);
        return;
    }
    int i = (blockIdx.x - nsc) * 256 + threadIdx.x;
    const float* W;
    int K, Nn, off, li;
    if (i < W2_OFF)       { W = W1; K = 256; Nn = 128; off = 0;      li = i; }
    else if (i < W3_OFF)  { W = W2; K = 128; Nn = 64;  off = W2_OFF; li = i - W2_OFF; }
    else if (i < WTOT)    { W = W3; K = 64;  Nn = 32;  off = W3_OFF; li = i - W3_OFF; }
    else return;
    int n = li / K, k = li - n * K;
    Wh[off + li] = __float2half_rn(__ldg(W + (size_t)k * Nn + n));
}

// ---------------------------------------------------------------------------
// Scan (exclusive) of deg -> rowptr; also emits dis = rsqrt(deg+1)
// ---------------------------------------------------------------------------
__global__ void k_scan_block(const int* __restrict__ deg, int* __restrict__ exc,
                             int* __restrict__ bsum, float* __restrict__ dis, int N)
{
    __shared__ int sh[1024];
    int i = blockIdx.x * 1024 + threadIdx.x;
    int v = (i < N) ? deg[i] : 0;
    sh[threadIdx.x] = v;
    __syncthreads();
#pragma unroll
    for (int o = 1; o < 1024; o <<= 1) {
        int t = (threadIdx.x >= o) ? sh[threadIdx.x - o] : 0;
        __syncthreads();
        sh[threadIdx.x] += t;
        __syncthreads();
    }
    if (i < N) {
        exc[i] = sh[threadIdx.x] - v;
        dis[i] = rsqrtf((float)v + 1.0f);
    }
    if (threadIdx.x == 1023) bsum[blockIdx.x] = sh[1023];
}

// Adds block offsets, mirrors rowptr->cursor, zeroes stats + grid-barrier counter
__global__ void k_scan_add2(int* __restrict__ rowptr, int* __restrict__ cursor,
                            const int* __restrict__ bsum, float* __restrict__ stats,
                            int nb, int N)
{
    __shared__ int sh[256];
    __shared__ int sexc[256];
    int t = threadIdx.x;
    int v = (t < nb) ? __ldg(bsum + t) : 0;
    sh[t] = v;
    __syncthreads();
#pragma unroll
    for (int o = 1; o < 256; o <<= 1) {
        int u = (t >= o) ? sh[t - o] : 0;
        __syncthreads();
        sh[t] += u;
        __syncthreads();
    }
    sexc[t] = sh[t] - v;
    __syncthreads();

    int i = blockIdx.x * 256 + t;
    if (i < N) {
        int val = rowptr[i] + sexc[i >> 10];
        rowptr[i] = val;
        cursor[i] = val;
    }
    if (blockIdx.x == 0) {
        for (int f = t; f < STTOT; f += 256) stats[f] = 0.0f;
        if (t == 0) g_bar = 0u;
    }
}

// ---------------------------------------------------------------------------
// MMA + ldmatrix helpers
// ---------------------------------------------------------------------------
__device__ __forceinline__ void mma16816(float* c, const uint32_t* a, const uint32_t* b)
{
    asm volatile(
        "mma.sync.aligned.m16n8k16.row.col.f32.f16.f16.f32 "
        "{%0,%1,%2,%3}, {%4,%5,%6,%7}, {%8,%9}, {%0,%1,%2,%3};"
        : "+f"(c[0]), "+f"(c[1]), "+f"(c[2]), "+f"(c[3])
        : "r"(a[0]), "r"(a[1]), "r"(a[2]), "r"(a[3]), "r"(b[0]), "r"(b[1]));
}
__device__ __forceinline__ void ldsm_x4(uint32_t* r, uint32_t addr)
{
    asm volatile("ldmatrix.sync.aligned.m8n8.x4.shared.b16 {%0,%1,%2,%3}, [%4];"
                 : "=r"(r[0]), "=r"(r[1]), "=r"(r[2]), "=r"(r[3]) : "r"(addr));
}
__device__ __forceinline__ void ldsm_x2(uint32_t* r, uint32_t addr)
{
    asm volatile("ldmatrix.sync.aligned.m8n8.x2.shared.b16 {%0,%1}, [%2];"
                 : "=r"(r[0]), "=r"(r[1]) : "r"(addr));
}

// ---------------------------------------------------------------------------
// 2-product split GEMM core (A fp32 hi/lo split; W fp16-rounded), identical
// math/tiling to the best R12 kernel. Shared memory carved from caller block.
// CG=true -> A read via ld.global.cg (mega-kernel coherence).
// bnp_s != nullptr -> fused BN+ReLU on A (scale/shift precomputed in smem).
// ---------------------------------------------------------------------------
template <int BN, bool CG>
__device__ __forceinline__ void gemm_body(
    char* sm, int bid, const float* __restrict__ A, const __half* __restrict__ Wh,
    __half* __restrict__ C16, const float* __restrict__ disv, int M, int K,
    const float* bnp_s)
{
    constexpr int BM = 64, BK = 32;
    constexpr int LDA = BK + 8;
    constexpr int MT = 2;
    constexpr int NT = BN / 32;
    constexpr int WNW = BN / 4;

    __half (*Ah)[LDA] = reinterpret_cast<__half(*)[LDA]>(sm);
    __half (*Al)[LDA] = reinterpret_cast<__half(*)[LDA]>(sm + BM * LDA * 2);
    __half (*Bh)[LDA] = reinterpret_cast<__half(*)[LDA]>(sm + 2 * BM * LDA * 2);

    const int tid  = threadIdx.x;
    const int warp = tid >> 5;
    const int lane = tid & 31;
    const int g    = lane >> 2;
    const int t4   = lane & 3;
    const int wmi  = warp & 1;
    const int wni  = warp >> 1;
    const int m0   = bid * BM;
    const bool has_bn = (bnp_s != nullptr);

    const uint32_t ah_base = (uint32_t)__cvta_generic_to_shared(&Ah[0][0]);
    const uint32_t al_base = (uint32_t)__cvta_generic_to_shared(&Al[0][0]);
    const uint32_t bh_base = (uint32_t)__cvta_generic_to_shared(&Bh[0][0]);
    const int arow = lane & 15;
    const int acol = (lane & 16) ? 8 : 0;
    const int brow = lane & 7;
    const int bcol = (lane & 8) ? 8 : 0;

    const int a_row0 = tid >> 3;
    const int a_row1 = (tid + 256) >> 3;
    const int a_c4   = tid & 7;

    auto ldA = [&](int k0, float4* r) {
        int gr0 = m0 + a_row0;
        int gr1 = m0 + a_row1;
        r[0] = (gr0 < M) ? (CG ? ldcg_f4(A + (size_t)gr0 * K + k0 + a_c4 * 4)
                               : *(const float4*)(A + (size_t)gr0 * K + k0 + a_c4 * 4))
                         : make_float4(0.f, 0.f, 0.f, 0.f);
        r[1] = (gr1 < M) ? (CG ? ldcg_f4(A + (size_t)gr1 * K + k0 + a_c4 * 4)
                               : *(const float4*)(A + (size_t)gr1 * K + k0 + a_c4 * 4))
                         : make_float4(0.f, 0.f, 0.f, 0.f);
    };

    auto stA = [&](float4* r, int k0) {
#pragma unroll
        for (int i = 0; i < 2; i++) {
            int row = (i == 0) ? a_row0 : a_row1;
            float4 v = r[i];
            if (has_bn) {
                int kidx = k0 + a_c4 * 4;
                float4 sc = *(const float4*)&bnp_s[kidx];
                float4 sh = *(const float4*)&bnp_s[K + kidx];
                v.x = fmaxf(fmaf(v.x, sc.x, sh.x), 0.f);
                v.y = fmaxf(fmaf(v.y, sc.y, sh.y), 0.f);
                v.z = fmaxf(fmaf(v.z, sc.z, sh.z), 0.f);
                v.w = fmaxf(fmaf(v.w, sc.w, sh.w), 0.f);
            }
            float f[4] = {v.x, v.y, v.z, v.w};
            __half h[4], l[4];
#pragma unroll
            for (int q = 0; q < 4; q++) {
                h[q] = __float2half_rn(f[q]);
                l[q] = __float2half_rn(f[q] - __half2float(h[q]));
            }
            uint2 uh, ul;
            ((__half2*)&uh)[0] = __halves2half2(h[0], h[1]);
            ((__half2*)&uh)[1] = __halves2half2(h[2], h[3]);
            ((__half2*)&ul)[0] = __halves2half2(l[0], l[1]);
            ((__half2*)&ul)[1] = __halves2half2(l[2], l[3]);
            *(uint2*)&Ah[row][a_c4 * 4] = uh;
            *(uint2*)&Al[row][a_c4 * 4] = ul;
        }
    };

    float acc[MT][NT][4];
#pragma unroll
    for (int mt = 0; mt < MT; mt++)
#pragma unroll
        for (int nt = 0; nt < NT; nt++)
#pragma unroll
            for (int q = 0; q < 4; q++) acc[mt][nt][q] = 0.0f;

    float4 cur[2];
    ldA(0, cur);

    for (int k0 = 0; k0 < K; k0 += BK) {
        stA(cur, k0);
#pragma unroll
        for (int i = 0; i < (BN * 4 + 255) / 256; i++) {
            int idx = tid + i * 256;
            if (idx < BN * 4) {
                int n  = idx >> 2;
                int c8 = idx & 3;
                *(uint4*)&Bh[n][c8 * 8] = *(const uint4*)(Wh + (size_t)n * K + k0 + c8 * 8);
            }
        }
        __syncthreads();

        float4 nxt[2];
        if (k0 + BK < K) ldA(k0 + BK, nxt);
        else { nxt[0] = make_float4(0.f,0.f,0.f,0.f); nxt[1] = nxt[0]; }

#pragma unroll
        for (int kk = 0; kk < BK; kk += 16) {
            uint32_t ah[MT][4], al[MT][4], bh[NT][2];
#pragma unroll
            for (int mt = 0; mt < MT; mt++) {
                uint32_t off = ((wmi * 32 + mt * 16 + arow) * LDA + kk + acol) * 2;
                ldsm_x4(ah[mt], ah_base + off);
                ldsm_x4(al[mt], al_base + off);
            }
#pragma unroll
            for (int nt = 0; nt < NT; nt++) {
                uint32_t off = ((wni * WNW + nt * 8 + brow) * LDA + kk + bcol) * 2;
                ldsm_x2(bh[nt], bh_base + off);
            }
#pragma unroll
            for (int mt = 0; mt < MT; mt++)
#pragma unroll
                for (int nt = 0; nt < NT; nt++) {
                    mma16816(acc[mt][nt], ah[mt], bh[nt]);
                    mma16816(acc[mt][nt], al[mt], bh[nt]);
                }
        }
        __syncthreads();
        cur[0] = nxt[0];
        cur[1] = nxt[1];
    }

#pragma unroll
    for (int mt = 0; mt < MT; mt++) {
#pragma unroll
        for (int nt = 0; nt < NT; nt++) {
            int r0 = m0 + wmi * 32 + mt * 16 + g;
            int r1 = r0 + 8;
            int c  = wni * WNW + nt * 8 + t4 * 2;
            if (r0 < M) {
                float d = __ldg(disv + r0);
                *(__half2*)&C16[(size_t)r0 * BN + c] =
                    __floats2half2_rn(acc[mt][nt][0] * d, acc[mt][nt][1] * d);
            }
            if (r1 < M) {
                float d = __ldg(disv + r1);
                *(__half2*)&C16[(size_t)r1 * BN + c] =
                    __floats2half2_rn(acc[mt][nt][2] * d, acc[mt][nt][3] * d);
            }
        }
    }
}

// Fused CSR scatter + layer-1 GEMM (own kernel, unchanged behavior)
__global__ __launch_bounds__(256) void k_scatter_gemm1(
    const int* __restrict__ ei, int* __restrict__ cursor, int* __restrict__ csr_src,
    int E, int ngemm,
    const float* __restrict__ A, const __half* __restrict__ Wh,
    __half* __restrict__ C16, const float* __restrict__ disv, int M)
{
    __shared__ __align__(16) char sm[20480];   // Ah+Al (10240) + Bh128 (10240)
    int b = blockIdx.x;
    bool is_gemm;
    int id;
    if (b < 2 * ngemm) { is_gemm = (b & 1); id = b >> 1; }
    else               { is_gemm = false;   id = b - ngemm; }
    if (!is_gemm) {
        int e = id * 256 + threadIdx.x;
        if (e < E) {
            int src = __ldg(ei + e);
            int dst = __ldg(ei + E + e);
            int pos = atomicAdd(&cursor[dst], 1);
            csr_src[pos] = src;
        }
        return;
    }
    gemm_body<128, false>(sm, id, A, Wh, C16, disv, M, 256, nullptr);
}

// ---------------------------------------------------------------------------
// Gather phase (device fn): CSR gather on fp16 rows + BN stats, looped over
// node-lane tasks with grid stride (stride % G == 0 keeps j fixed per thread).
// All mutable-buffer reads via ld.global.cg.
// ---------------------------------------------------------------------------
template <int F>
__device__ void gather_phase(char* sm,
    const int* __restrict__ rowptr, const int* __restrict__ deg,
    const int* __restrict__ csr_src, const __half* __restrict__ h16,
    const float* __restrict__ dis, const float* __restrict__ bias,
    float* __restrict__ agg, float* __restrict__ stats, int N, int grid256)
{
    constexpr int G = F / 8;
    float* ssum = (float*)sm;
    float* ssq  = ssum + F;
    const int tid = threadIdx.x;
    if (tid < F) { ssum[tid] = 0.0f; ssq[tid] = 0.0f; }
    __syncthreads();

    const int j = tid % G;
    const __half* base = h16 + j * 8;
    float4 b0 = __ldg((const float4*)(bias + j * 8));
    float4 b1 = __ldg((const float4*)(bias + j * 8) + 1);

    float ts[8], tq[8];
#pragma unroll
    for (int q = 0; q < 8; q++) { ts[q] = 0.0f; tq[q] = 0.0f; }

    for (int t = blockIdx.x * 256 + tid; t < N * G; t += grid256) {
        int node  = t / G;
        int start = __ldg(rowptr + node);
        int cnt   = __ldg(deg + node);

        float a[8];
#pragma unroll
        for (int q = 0; q < 8; q++) a[q] = 0.0f;

        auto addv = [&](uint4 v) {
            const __half2* hv = (const __half2*)&v;
#pragma unroll
            for (int q = 0; q < 4; q++) {
                float2 f = __half22float2(hv[q]);
                a[2 * q]     += f.x;
                a[2 * q + 1] += f.y;
            }
        };

        int p = 0;
        for (; p + 4 <= cnt; p += 4) {
            int s0 = __ldg(csr_src + start + p);
            int s1 = __ldg(csr_src + start + p + 1);
            int s2 = __ldg(csr_src + start + p + 2);
            int s3 = __ldg(csr_src + start + p + 3);
            uint4 v0 = ldcg_u4(base + (size_t)s0 * F);
            uint4 v1 = ldcg_u4(base + (size_t)s1 * F);
            uint4 v2 = ldcg_u4(base + (size_t)s2 * F);
            uint4 v3 = ldcg_u4(base + (size_t)s3 * F);
            addv(v0); addv(v1); addv(v2); addv(v3);
        }
        for (; p < cnt; p++) {
            int s = __ldg(csr_src + start + p);
            addv(ldcg_u4(base + (size_t)s * F));
        }
        addv(ldcg_u4(base + (size_t)node * F));   // self-loop

        float d = __ldg(dis + node);
        float r[8];
        r[0] = fmaf(d, a[0], b0.x); r[1] = fmaf(d, a[1], b0.y);
        r[2] = fmaf(d, a[2], b0.z); r[3] = fmaf(d, a[3], b0.w);
        r[4] = fmaf(d, a[4], b1.x); r[5] = fmaf(d, a[5], b1.y);
        r[6] = fmaf(d, a[6], b1.z); r[7] = fmaf(d, a[7], b1.w);

        float4* o = (float4*)(agg + (size_t)node * F + j * 8);
        o[0] = make_float4(r[0], r[1], r[2], r[3]);
        o[1] = make_float4(r[4], r[5], r[6], r[7]);

#pragma unroll
        for (int q = 0; q < 8; q++) {
            ts[q] += r[q];
            tq[q] = fmaf(r[q], r[q], tq[q]);
        }
    }

#pragma unroll
    for (int o = 16; o >= G; o >>= 1) {
#pragma unroll
        for (int q = 0; q < 8; q++) {
            ts[q] += __shfl_xor_sync(0xFFFFFFFFu, ts[q], o);
            tq[q] += __shfl_xor_sync(0xFFFFFFFFu, tq[q], o);
        }
    }
    int lane = tid & 31;
    if (lane < G) {
#pragma unroll
        for (int q = 0; q < 8; q++) {
            atomicAdd(&ssum[lane * 8 + q], ts[q]);
            atomicAdd(&ssq[lane * 8 + q],  tq[q]);
        }
    }
    __syncthreads();
    if (tid < F) {
        atomicAdd(&stats[tid],     ssum[tid]);
        atomicAdd(&stats[F + tid], ssq[tid]);
    }
}

// BN scale/shift prep into shared (stats read via .cg)
__device__ void bn_prep(float* bnp_s, int K, int Nn, const float* stats,
                        const float* __restrict__ gam, const float* __restrict__ bt)
{
    float inv_n = 1.0f / (float)Nn;
    for (int f = threadIdx.x; f < K; f += 256) {
        float mu  = ldcg_f(stats + f) * inv_n;
        float var = fmaxf(ldcg_f(stats + K + f) * inv_n - mu * mu, 0.0f);
        float sc  = gam[f] * rsqrtf(var + 1e-5f);
        bnp_s[f]     = sc;
        bnp_s[K + f] = bt[f] - mu * sc;
    }
}

// ---------------------------------------------------------------------------
// Persistent mega-kernel: gather1 | gemm2 | gather2 | gemm3 | gather3 | fc
// ---------------------------------------------------------------------------
__global__ __launch_bounds__(256) void k_mega(
    const int* __restrict__ rowptr, const int* __restrict__ deg,
    const int* __restrict__ csr, __half* __restrict__ h16,
    float* __restrict__ agg, float* __restrict__ stats,
    const float* __restrict__ dis, const __half* __restrict__ whi,
    const float* __restrict__ b1, const float* __restrict__ g1, const float* __restrict__ bt1,
    const float* __restrict__ b2, const float* __restrict__ g2, const float* __restrict__ bt2,
    const float* __restrict__ b3, const float* __restrict__ g3, const float* __restrict__ bt3,
    const float* __restrict__ Wfc, const float* __restrict__ bfc,
    float* __restrict__ out, int N, int nblocks)
{
    __shared__ __align__(16) char sm[17408];   // Ah+Al (10240) + Bh64 (5120) + bnp (2048)
    float* bnp_s = (float*)(sm + 15360);
    const int grid256 = nblocks * 256;
    const unsigned nb = (unsigned)nblocks;

    // P0: layer-1 gather (F=128)
    gather_phase<128>(sm, rowptr, deg, csr, h16, dis, b1, agg, stats, N, grid256);
    grid_barrier(1u * nb);

    // P1: layer-2 GEMM (128 -> 64), fused BN+ReLU
    bn_prep(bnp_s, 128, N, stats, g1, bt1);
    __syncthreads();
    {
        int ntiles = (N + 63) >> 6;
        for (int b = blockIdx.x; b < ntiles; b += nblocks)
            gemm_body<64, true>(sm, b, agg, whi + W2_OFF, h16, dis, N, 128, bnp_s);
    }
    grid_barrier(2u * nb);

    // P2: layer-2 gather (F=64)
    gather_phase<64>(sm, rowptr, deg, csr, h16, dis, b2, agg, stats + ST2, N, grid256);
    grid_barrier(3u * nb);

    // P3: layer-3 GEMM (64 -> 32), fused BN+ReLU
    bn_prep(bnp_s, 64, N, stats + ST2, g2, bt2);
    __syncthreads();
    {
        int ntiles = (N + 63) >> 6;
        for (int b = blockIdx.x; b < ntiles; b += nblocks)
            gemm_body<32, true>(sm, b, agg, whi + W3_OFF, h16, dis, N, 64, bnp_s);
    }
    grid_barrier(4u * nb);

    // P4: layer-3 gather (F=32)
    gather_phase<32>(sm, rowptr, deg, csr, h16, dis, b3, agg, stats + ST3, N, grid256);
    grid_barrier(5u * nb);

    // P5: final FC with in-kernel BN finalize + ReLU
    {
        float* sc_s = (float*)sm;
        float* sh_s = sc_s + 32;
        int tid = threadIdx.x;
        if (tid < 32) {
            float inv_n = 1.0f / (float)N;
            float mu  = ldcg_f(stats + ST3 + tid) * inv_n;
            float var = fmaxf(ldcg_f(stats + ST3 + 32 + tid) * inv_n - mu * mu, 0.0f);
            float sc  = g3[tid] * rsqrtf(var + 1e-5f);
            sc_s[tid] = sc;
            sh_s[tid] = bt3[tid] - mu * sc;
        }
        __syncthreads();
        int lane = tid & 31;
        for (int node = blockIdx.x * 8 + (tid >> 5); node < N; node += nblocks * 8) {
            float hv = ldcg_f(agg + (size_t)node * 32 + lane);
            float v = fmaxf(fmaf(hv, sc_s[lane], sh_s[lane]), 0.0f) * __ldg(Wfc + lane);
#pragma unroll
            for (int o = 16; o; o >>= 1) v += __shfl_down_sync(0xFFFFFFFFu, v, o);
            if (lane == 0) out[node] = v + __ldg(bfc);
        }
    }
}

// ---------------------------------------------------------------------------
static inline int cdiv(long long a, long long b) { return (int)((a + b - 1) / b); }

extern "C" void kernel_launch(void* const* d_in, const int* in_sizes, int n_in,
                              void* d_out, int out_size)
{
    const float* x   = (const float*)d_in[0];
    const int*   ei  = (const int*)d_in[1];
    const float* W1  = (const float*)d_in[2];
    const float* b1  = (const float*)d_in[3];
    const float* g1  = (const float*)d_in[4];
    const float* bt1 = (const float*)d_in[5];
    const float* W2  = (const float*)d_in[6];
    const float* b2  = (const float*)d_in[7];
    const float* g2  = (const float*)d_in[8];
    const float* bt2 = (const float*)d_in[9];
    const float* W3  = (const float*)d_in[10];
    const float* b3  = (const float*)d_in[11];
    const float* g3  = (const float*)d_in[12];
    const float* bt3 = (const float*)d_in[13];
    const float* Wfc = (const float*)d_in[14];
    const float* bfc = (const float*)d_in[15];
    float* out = (float*)d_out;

    const int N = in_sizes[0] / 256;
    const int E = in_sizes[1] / 2;

    float *agg, *dis, *stats;
    __half *h16, *whi;
    int *deg, *rowptr, *cursor, *bsum, *csr;
    cudaGetSymbolAddress((void**)&agg,    g_agg);
    cudaGetSymbolAddress((void**)&h16,    g_h16);
    cudaGetSymbolAddress((void**)&dis,    g_dis);
    cudaGetSymbolAddress((void**)&deg,    g_deg);
    cudaGetSymbolAddress((void**)&rowptr, g_rowptr);
    cudaGetSymbolAddress((void**)&cursor, g_cursor);
    cudaGetSymbolAddress((void**)&bsum,   g_bsum);
    cudaGetSymbolAddress((void**)&csr,    g_csr_src);
    cudaGetSymbolAddress((void**)&stats,  g_stats);
    cudaGetSymbolAddress((void**)&whi,    g_whi);

    const int nsc   = cdiv(E, 256);
    const int nw    = cdiv(WTOT, 256);
    const int nb    = cdiv(N, 1024);
    const int ngemm = cdiv(N, 64);

    // Persistent grid size: all blocks must be co-resident (no deadlock)
    int bpm = 0;
    cudaOccupancyMaxActiveBlocksPerMultiprocessor(&bpm, k_mega, 256, 0);
    if (bpm < 1) bpm = 1;
    int devid = 0;
    cudaGetDevice(&devid);
    int smcount = 148;
    cudaDeviceGetAttribute(&smcount, cudaDevAttrMultiProcessorCount, devid);
    const int nblocks = bpm * smcount;

    // ---- prologue ----
    cudaMemsetAsync(deg, 0, (size_t)N * sizeof(int));
    k_pro1<<<nsc + nw, 256>>>(ei, deg, E, nsc, W1, W2, W3, whi);
    k_scan_block<<<nb, 1024>>>(deg, rowptr, bsum, dis, N);
    k_scan_add2<<<cdiv(N, 256), 256>>>(rowptr, cursor, bsum, stats, nb, N);
    k_scatter_gemm1<<<ngemm + nsc, 256>>>(ei, cursor, csr, E, ngemm,
                                          x, whi, h16, dis, N);

    // ---- persistent mega-kernel: everything else in one launch ----
    k_mega<<<nblocks, 256>>>(rowptr, deg, csr, h16, agg, stats, dis, whi,
                             b1, g1, bt1, b2, g2, bt2, b3, g3, bt3,
                             Wfc, bfc, out, N, nblocks);
}

// round 16
// speedup vs baseline: 1.1046x; 1.0461x over previous
#include <cuda_runtime.h>
#include <cuda_fp16.h>
#include <cuda_bf16.h>
#include <cstdint>

#define MAXN 100000
#define MAXE 3200000
#define MAXF 128

#define W2_OFF (256 * 128)
#define W3_OFF (256 * 128 + 128 * 64)
#define WTOT   (256 * 128 + 128 * 64 + 64 * 32)

// stats regions: [0,256) layer1 (F=128), [256,384) layer2 (F=64), [384,448) layer3 (F=32)
#define ST2 256
#define ST3 384
#define STTOT 448

// Scratch (device globals; no cudaMalloc allowed)
__device__ float  g_agg[(size_t)MAXN * MAXF];        // fp32 aggregation output
__device__ __half g_h16[(size_t)MAXN * MAXF];        // fp16 dis-prescaled features
__device__ float  g_dis[MAXN];
__device__ int    g_deg[MAXN];
__device__ int    g_rowptr[MAXN + 1];
__device__ int    g_cursor[MAXN + 1];
__device__ int    g_bsum[256];
__device__ int    g_csr_src[MAXE];
__device__ float  g_stats[STTOT];
__device__ __half g_whi[WTOT];

// ---------------------------------------------------------------------------
// Prologue 1: fused degree count + weight fp16 round/transpose
// ---------------------------------------------------------------------------
__global__ void k_pro1(const int* __restrict__ ei, int* __restrict__ deg, int E, int nsc,
                       const float* __restrict__ W1, const float* __restrict__ W2,
                       const float* __restrict__ W3, __half* __restrict__ Wh)
{
    if ((int)blockIdx.x < nsc) {
        int e = blockIdx.x * 256 + threadIdx.x;
        if (e < E) atomicAdd(&deg[__ldg(ei + E + e)], 1);
        return;
    }
    int i = (blockIdx.x - nsc) * 256 + threadIdx.x;
    const float* W;
    int K, Nn, off, li;
    if (i < W2_OFF)       { W = W1; K = 256; Nn = 128; off = 0;      li = i; }
    else if (i < W3_OFF)  { W = W2; K = 128; Nn = 64;  off = W2_OFF; li = i - W2_OFF; }
    else if (i < WTOT)    { W = W3; K = 64;  Nn = 32;  off = W3_OFF; li = i - W3_OFF; }
    else return;
    int n = li / K, k = li - n * K;
    Wh[off + li] = __float2half_rn(__ldg(W + (size_t)k * Nn + n));
}

// ---------------------------------------------------------------------------
// Scan (exclusive) of deg -> rowptr; also emits dis = rsqrt(deg+1)
// ---------------------------------------------------------------------------
__global__ void k_scan_block(const int* __restrict__ deg, int* __restrict__ exc,
                             int* __restrict__ bsum, float* __restrict__ dis, int N)
{
    __shared__ int sh[1024];
    int i = blockIdx.x * 1024 + threadIdx.x;
    int v = (i < N) ? deg[i] : 0;
    sh[threadIdx.x] = v;
    __syncthreads();
#pragma unroll
    for (int o = 1; o < 1024; o <<= 1) {
        int t = (threadIdx.x >= o) ? sh[threadIdx.x - o] : 0;
        __syncthreads();
        sh[threadIdx.x] += t;
        __syncthreads();
    }
    if (i < N) {
        exc[i] = sh[threadIdx.x] - v;
        dis[i] = rsqrtf((float)v + 1.0f);
    }
    if (threadIdx.x == 1023) bsum[blockIdx.x] = sh[1023];
}

// Adds block offsets (bsum scanned redundantly per block in smem),
// mirrors rowptr->cursor, zeroes ALL BN stats regions.
__global__ void k_scan_add2(int* __restrict__ rowptr, int* __restrict__ cursor,
                            const int* __restrict__ bsum, float* __restrict__ stats,
                            int nb, int N)
{
    __shared__ int sh[256];
    __shared__ int sexc[256];
    int t = threadIdx.x;
    int v = (t < nb) ? __ldg(bsum + t) : 0;
    sh[t] = v;
    __syncthreads();
#pragma unroll
    for (int o = 1; o < 256; o <<= 1) {
        int u = (t >= o) ? sh[t - o] : 0;
        __syncthreads();
        sh[t] += u;
        __syncthreads();
    }
    sexc[t] = sh[t] - v;   // exclusive prefix of bsum
    __syncthreads();

    int i = blockIdx.x * 256 + t;
    if (i < N) {
        int val = rowptr[i] + sexc[i >> 10];
        rowptr[i] = val;
        cursor[i] = val;
    }
    if (blockIdx.x == 0) {
        for (int f = t; f < STTOT; f += 256) stats[f] = 0.0f;
    }
}

// ---------------------------------------------------------------------------
// MMA + ldmatrix helpers
// ---------------------------------------------------------------------------
__device__ __forceinline__ void mma16816(float* c, const uint32_t* a, const uint32_t* b)
{
    asm volatile(
        "mma.sync.aligned.m16n8k16.row.col.f32.f16.f16.f32 "
        "{%0,%1,%2,%3}, {%4,%5,%6,%7}, {%8,%9}, {%0,%1,%2,%3};"
        : "+f"(c[0]), "+f"(c[1]), "+f"(c[2]), "+f"(c[3])
        : "r"(a[0]), "r"(a[1]), "r"(a[2]), "r"(a[3]), "r"(b[0]), "r"(b[1]));
}
__device__ __forceinline__ void ldsm_x4(uint32_t* r, uint32_t addr)
{
    asm volatile("ldmatrix.sync.aligned.m8n8.x4.shared.b16 {%0,%1,%2,%3}, [%4];"
                 : "=r"(r[0]), "=r"(r[1]), "=r"(r[2]), "=r"(r[3]) : "r"(addr));
}
__device__ __forceinline__ void ldsm_x2(uint32_t* r, uint32_t addr)
{
    asm volatile("ldmatrix.sync.aligned.m8n8.x2.shared.b16 {%0,%1}, [%2];"
                 : "=r"(r[0]), "=r"(r[1]) : "r"(addr));
}

// ---------------------------------------------------------------------------
// GEMM core (W fp16-rounded), ldmatrix fragments, register-pipelined A loads:
//   C16[M,BN] = half( dis[m] * (BNReLU?(A[M,K]) @ W16[K,BN]) )
// SPLIT=true : A split to hi+lo fp16, 2 MMA products (fp32-accurate A)
// SPLIT=false: A fp16-rounded, 1 MMA product (layer-1 only)
// BM=64, BK=32, 256 threads (8 warps 2x4), warp tile 32 x (BN/4).
// ---------------------------------------------------------------------------
template <int BN, bool SPLIT>
__device__ __forceinline__ void gemm_body(
    int bid, const float* __restrict__ A, const __half* __restrict__ Wh,
    __half* __restrict__ C16, const float* __restrict__ disv, int M, int K,
    const float* __restrict__ stats, const float* __restrict__ gam,
    const float* __restrict__ bt)
{
    constexpr int BM = 64, BK = 32;
    constexpr int LDA = BK + 8;           // halfs; 80B row stride
    constexpr int MT = 2;
    constexpr int NT = BN / 32;
    constexpr int WNW = BN / 4;

    __shared__ __align__(16) __half Ah[BM][LDA];
    __shared__ __align__(16) __half Al[SPLIT ? BM : 1][LDA];
    __shared__ __align__(16) __half Bh[BN][LDA];
    __shared__ __align__(16) float bnp_s[512];   // [K] scale | [K] shift

    const int tid  = threadIdx.x;
    const int warp = tid >> 5;
    const int lane = tid & 31;
    const int g    = lane >> 2;
    const int t4   = lane & 3;
    const int wmi  = warp & 1;
    const int wni  = warp >> 1;
    const int m0   = bid * BM;
    const bool has_bn = (stats != nullptr);

    const uint32_t ah_base = (uint32_t)__cvta_generic_to_shared(&Ah[0][0]);
    const uint32_t al_base = (uint32_t)__cvta_generic_to_shared(&Al[0][0]);
    const uint32_t bh_base = (uint32_t)__cvta_generic_to_shared(&Bh[0][0]);
    const int arow = lane & 15;
    const int acol = (lane & 16) ? 8 : 0;
    const int brow = lane & 7;
    const int bcol = (lane & 8) ? 8 : 0;

    if (has_bn) {
        float inv_n = 1.0f / (float)M;
        for (int f = tid; f < K; f += 256) {
            float mu  = stats[f] * inv_n;
            float var = fmaxf(stats[K + f] * inv_n - mu * mu, 0.0f);
            float sc  = gam[f] * rsqrtf(var + 1e-5f);
            bnp_s[f]     = sc;
            bnp_s[K + f] = bt[f] - mu * sc;
        }
    }
    __syncthreads();

    // A staging: 64x32 floats = 512 float4, 2 per thread
    const int a_row0 = tid >> 3;
    const int a_row1 = (tid + 256) >> 3;
    const int a_c4   = tid & 7;

    auto ldA = [&](int k0, float4* r) {
        int gr0 = m0 + a_row0;
        int gr1 = m0 + a_row1;
        r[0] = (gr0 < M) ? *(const float4*)(A + (size_t)gr0 * K + k0 + a_c4 * 4)
                         : make_float4(0.f, 0.f, 0.f, 0.f);
        r[1] = (gr1 < M) ? *(const float4*)(A + (size_t)gr1 * K + k0 + a_c4 * 4)
                         : make_float4(0.f, 0.f, 0.f, 0.f);
    };

    auto stA = [&](float4* r, int k0) {
#pragma unroll
        for (int i = 0; i < 2; i++) {
            int row = (i == 0) ? a_row0 : a_row1;
            float4 v = r[i];
            if (has_bn) {
                int kidx = k0 + a_c4 * 4;
                float4 sc = *(const float4*)&bnp_s[kidx];
                float4 sh = *(const float4*)&bnp_s[K + kidx];
                v.x = fmaxf(fmaf(v.x, sc.x, sh.x), 0.f);
                v.y = fmaxf(fmaf(v.y, sc.y, sh.y), 0.f);
                v.z = fmaxf(fmaf(v.z, sc.z, sh.z), 0.f);
                v.w = fmaxf(fmaf(v.w, sc.w, sh.w), 0.f);
            }
            float f[4] = {v.x, v.y, v.z, v.w};
            __half h[4];
#pragma unroll
            for (int q = 0; q < 4; q++) h[q] = __float2half_rn(f[q]);
            uint2 uh;
            ((__half2*)&uh)[0] = __halves2half2(h[0], h[1]);
            ((__half2*)&uh)[1] = __halves2half2(h[2], h[3]);
            *(uint2*)&Ah[row][a_c4 * 4] = uh;
            if (SPLIT) {
                __half l[4];
#pragma unroll
                for (int q = 0; q < 4; q++)
                    l[q] = __float2half_rn(f[q] - __half2float(h[q]));
                uint2 ul;
                ((__half2*)&ul)[0] = __halves2half2(l[0], l[1]);
                ((__half2*)&ul)[1] = __halves2half2(l[2], l[3]);
                *(uint2*)&Al[row][a_c4 * 4] = ul;
            }
        }
    };

    float acc[MT][NT][4];
#pragma unroll
    for (int mt = 0; mt < MT; mt++)
#pragma unroll
        for (int nt = 0; nt < NT; nt++)
#pragma unroll
            for (int q = 0; q < 4; q++) acc[mt][nt][q] = 0.0f;

    float4 cur[2];
    ldA(0, cur);

    for (int k0 = 0; k0 < K; k0 += BK) {
        stA(cur, k0);
        // ---- stage B tile (fp16, transposed [BN][K]; L2-resident) ----
#pragma unroll
        for (int i = 0; i < (BN * 4 + 255) / 256; i++) {
            int idx = tid + i * 256;
            if (idx < BN * 4) {
                int n  = idx >> 2;
                int c8 = idx & 3;
                *(uint4*)&Bh[n][c8 * 8] = *(const uint4*)(Wh + (size_t)n * K + k0 + c8 * 8);
            }
        }
        __syncthreads();

        // ---- prefetch next A tile into registers (LDGs overlap compute) ----
        float4 nxt[2];
        if (k0 + BK < K) ldA(k0 + BK, nxt);
        else { nxt[0] = make_float4(0.f,0.f,0.f,0.f); nxt[1] = nxt[0]; }

#pragma unroll
        for (int kk = 0; kk < BK; kk += 16) {
            uint32_t ah[MT][4], al[SPLIT ? MT : 1][4], bh[NT][2];
#pragma unroll
            for (int mt = 0; mt < MT; mt++) {
                uint32_t off = ((wmi * 32 + mt * 16 + arow) * LDA + kk + acol) * 2;
                ldsm_x4(ah[mt], ah_base + off);
                if (SPLIT) ldsm_x4(al[mt], al_base + off);
            }
#pragma unroll
            for (int nt = 0; nt < NT; nt++) {
                uint32_t off = ((wni * WNW + nt * 8 + brow) * LDA + kk + bcol) * 2;
                ldsm_x2(bh[nt], bh_base + off);
            }
#pragma unroll
            for (int mt = 0; mt < MT; mt++)
#pragma unroll
                for (int nt = 0; nt < NT; nt++) {
                    mma16816(acc[mt][nt], ah[mt], bh[nt]);
                    if (SPLIT) mma16816(acc[mt][nt], al[mt], bh[nt]);
                }
        }
        __syncthreads();
        cur[0] = nxt[0];
        cur[1] = nxt[1];
    }

    // ---- epilogue: scale by dis, convert to fp16, store ----
#pragma unroll
    for (int mt = 0; mt < MT; mt++) {
#pragma unroll
        for (int nt = 0; nt < NT; nt++) {
            int r0 = m0 + wmi * 32 + mt * 16 + g;
            int r1 = r0 + 8;
            int c  = wni * WNW + nt * 8 + t4 * 2;
            if (r0 < M) {
                float d = __ldg(disv + r0);
                *(__half2*)&C16[(size_t)r0 * BN + c] =
                    __floats2half2_rn(acc[mt][nt][0] * d, acc[mt][nt][1] * d);
            }
            if (r1 < M) {
                float d = __ldg(disv + r1);
                *(__half2*)&C16[(size_t)r1 * BN + c] =
                    __floats2half2_rn(acc[mt][nt][2] * d, acc[mt][nt][3] * d);
            }
        }
    }
}

template <int BN>
__global__ __launch_bounds__(256) void k_mma_gemm(
    const float* __restrict__ A, const __half* __restrict__ Wh,
    __half* __restrict__ C16, const float* __restrict__ disv, int M, int K,
    const float* __restrict__ stats, const float* __restrict__ gam,
    const float* __restrict__ bt)
{
    gemm_body<BN, true>(blockIdx.x, A, Wh, C16, disv, M, K, stats, gam, bt);
}

// Fused CSR scatter + layer-1 GEMM (single-product fp16 A; 4 blocks/SM)
__global__ __launch_bounds__(256, 4) void k_scatter_gemm1(
    const int* __restrict__ ei, int* __restrict__ cursor, int* __restrict__ csr_src,
    int E, int ngemm,
    const float* __restrict__ A, const __half* __restrict__ Wh,
    __half* __restrict__ C16, const float* __restrict__ disv, int M)
{
    int b = blockIdx.x;
    bool is_gemm;
    int id;
    if (b < 2 * ngemm) { is_gemm = (b & 1); id = b >> 1; }
    else               { is_gemm = false;   id = b - ngemm; }
    if (!is_gemm) {
        int e = id * 256 + threadIdx.x;
        if (e < E) {
            int src = __ldg(ei + e);
            int dst = __ldg(ei + E + e);
            int pos = atomicAdd(&cursor[dst], 1);
            csr_src[pos] = src;
        }
        return;
    }
    gemm_body<128, false>(id, A, Wh, C16, disv, M, 256, nullptr, nullptr, nullptr);
}

// ---------------------------------------------------------------------------
// CSR gather on fp16 prescaled rows + fused BN statistics (4-edge unroll).
// Output agg is fp32.
// ---------------------------------------------------------------------------
template <int F>
__global__ __launch_bounds__(256) void k_gather16(
    const int* __restrict__ rowptr, const int* __restrict__ deg,
    const int* __restrict__ csr_src, const __half* __restrict__ h16,
    const float* __restrict__ dis, const float* __restrict__ bias,
    float* __restrict__ agg, float* __restrict__ stats, int N)
{
    constexpr int G = F / 8;
    __shared__ float ssum[F];
    __shared__ float ssq[F];
    const int tid = threadIdx.x;
    if (tid < F) { ssum[tid] = 0.0f; ssq[tid] = 0.0f; }
    __syncthreads();

    int t    = blockIdx.x * 256 + tid;
    int node = t / G;
    int j    = t - node * G;
    const bool valid = node < N;
    const int cn = valid ? node : 0;

    int start = __ldg(rowptr + cn);
    int cnt   = valid ? __ldg(deg + cn) : 0;
    const __half* base = h16 + j * 8;

    float a[8];
#pragma unroll
    for (int q = 0; q < 8; q++) a[q] = 0.0f;

    auto addv = [&](uint4 v) {
        const __half2* hv = (const __half2*)&v;
#pragma unroll
        for (int q = 0; q < 4; q++) {
            float2 f = __half22float2(hv[q]);
            a[2 * q]     += f.x;
            a[2 * q + 1] += f.y;
        }
    };

    int p = 0;
    for (; p + 4 <= cnt; p += 4) {
        int s0 = __ldg(csr_src + start + p);
        int s1 = __ldg(csr_src + start + p + 1);
        int s2 = __ldg(csr_src + start + p + 2);
        int s3 = __ldg(csr_src + start + p + 3);
        uint4 v0 = __ldg((const uint4*)(base + (size_t)s0 * F));
        uint4 v1 = __ldg((const uint4*)(base + (size_t)s1 * F));
        uint4 v2 = __ldg((const uint4*)(base + (size_t)s2 * F));
        uint4 v3 = __ldg((const uint4*)(base + (size_t)s3 * F));
        addv(v0); addv(v1); addv(v2); addv(v3);
    }
    for (; p < cnt; p++) {
        int s = __ldg(csr_src + start + p);
        addv(__ldg((const uint4*)(base + (size_t)s * F)));
    }
    if (valid) addv(__ldg((const uint4*)(base + (size_t)cn * F)));  // self-loop

    float d = valid ? __ldg(dis + cn) : 0.0f;
    float4 b0 = __ldg((const float4*)(bias + j * 8));
    float4 b1 = __ldg((const float4*)(bias + j * 8) + 1);
    float r[8];
    r[0] = fmaf(d, a[0], b0.x); r[1] = fmaf(d, a[1], b0.y);
    r[2] = fmaf(d, a[2], b0.z); r[3] = fmaf(d, a[3], b0.w);
    r[4] = fmaf(d, a[4], b1.x); r[5] = fmaf(d, a[5], b1.y);
    r[6] = fmaf(d, a[6], b1.z); r[7] = fmaf(d, a[7], b1.w);

    if (valid) {
        float4* o = (float4*)(agg + (size_t)node * F + j * 8);
        o[0] = make_float4(r[0], r[1], r[2], r[3]);
        o[1] = make_float4(r[4], r[5], r[6], r[7]);
    } else {
#pragma unroll
        for (int q = 0; q < 8; q++) r[q] = 0.0f;
    }

    float s2v[8];
#pragma unroll
    for (int q = 0; q < 8; q++) s2v[q] = r[q] * r[q];
#pragma unroll
    for (int o = 16; o >= G; o >>= 1) {
#pragma unroll
        for (int q = 0; q < 8; q++) {
            r[q]   += __shfl_xor_sync(0xFFFFFFFFu, r[q],   o);
            s2v[q] += __shfl_xor_sync(0xFFFFFFFFu, s2v[q], o);
        }
    }
    int lane = tid & 31;
    if (lane < G) {
#pragma unroll
        for (int q = 0; q < 8; q++) {
            atomicAdd(&ssum[lane * 8 + q], r[q]);
            atomicAdd(&ssq[lane * 8 + q],  s2v[q]);
        }
    }
    __syncthreads();
    if (tid < F) {
        atomicAdd(&stats[tid],     ssum[tid]);
        atomicAdd(&stats[F + tid], ssq[tid]);
    }
}

// ---------------------------------------------------------------------------
// Final FC with in-kernel BN finalize + fused BN+ReLU (fp32 input)
// ---------------------------------------------------------------------------
__global__ void k_final_fc(const float* __restrict__ h, const float* __restrict__ stats,
                           const float* __restrict__ gam, const float* __restrict__ bt,
                           const float* __restrict__ W, const float* __restrict__ b,
                           float* __restrict__ out, int N)
{
    __shared__ float sc_s[32], sh_s[32];
    int tid = threadIdx.x;
    if (tid < 32) {
        float inv_n = 1.0f / (float)N;
        float mu  = stats[tid] * inv_n;
        float var = fmaxf(stats[32 + tid] * inv_n - mu * mu, 0.0f);
        float sc  = gam[tid] * rsqrtf(var + 1e-5f);
        sc_s[tid] = sc;
        sh_s[tid] = bt[tid] - mu * sc;
    }
    __syncthreads();
    int lane = tid & 31;
    int node = (blockIdx.x * blockDim.x + tid) >> 5;
    if (node >= N) return;
    float v = fmaxf(fmaf(h[(size_t)node * 32 + lane], sc_s[lane], sh_s[lane]), 0.0f)
              * __ldg(W + lane);
#pragma unroll
    for (int o = 16; o; o >>= 1) v += __shfl_down_sync(0xFFFFFFFFu, v, o);
    if (lane == 0) out[node] = v + __ldg(b);
}

// ---------------------------------------------------------------------------
static inline int cdiv(long long a, long long b) { return (int)((a + b - 1) / b); }

extern "C" void kernel_launch(void* const* d_in, const int* in_sizes, int n_in,
                              void* d_out, int out_size)
{
    const float* x   = (const float*)d_in[0];
    const int*   ei  = (const int*)d_in[1];
    const float* W1  = (const float*)d_in[2];
    const float* b1  = (const float*)d_in[3];
    const float* g1  = (const float*)d_in[4];
    const float* bt1 = (const float*)d_in[5];
    const float* W2  = (const float*)d_in[6];
    const float* b2  = (const float*)d_in[7];
    const float* g2  = (const float*)d_in[8];
    const float* bt2 = (const float*)d_in[9];
    const float* W3  = (const float*)d_in[10];
    const float* b3  = (const float*)d_in[11];
    const float* g3  = (const float*)d_in[12];
    const float* bt3 = (const float*)d_in[13];
    const float* Wfc = (const float*)d_in[14];
    const float* bfc = (const float*)d_in[15];
    float* out = (float*)d_out;

    const int N = in_sizes[0] / 256;
    const int E = in_sizes[1] / 2;

    float *agg, *dis, *stats;
    __half *h16, *whi;
    int *deg, *rowptr, *cursor, *bsum, *csr;
    cudaGetSymbolAddress((void**)&agg,    g_agg);
    cudaGetSymbolAddress((void**)&h16,    g_h16);
    cudaGetSymbolAddress((void**)&dis,    g_dis);
    cudaGetSymbolAddress((void**)&deg,    g_deg);
    cudaGetSymbolAddress((void**)&rowptr, g_rowptr);
    cudaGetSymbolAddress((void**)&cursor, g_cursor);
    cudaGetSymbolAddress((void**)&bsum,   g_bsum);
    cudaGetSymbolAddress((void**)&csr,    g_csr_src);
    cudaGetSymbolAddress((void**)&stats,  g_stats);
    cudaGetSymbolAddress((void**)&whi,    g_whi);

    const int nsc   = cdiv(E, 256);
    const int nw    = cdiv(WTOT, 256);
    const int nb    = cdiv(N, 1024);
    const int ngemm = cdiv(N, 64);

    // ---- prologue: degree count + weight round, scan(+dis), scatter+GEMM1 ----
    cudaMemsetAsync(deg, 0, (size_t)N * sizeof(int));
    k_pro1<<<nsc + nw, 256>>>(ei, deg, E, nsc, W1, W2, W3, whi);
    k_scan_block<<<nb, 1024>>>(deg, rowptr, bsum, dis, N);
    k_scan_add2<<<cdiv(N, 256), 256>>>(rowptr, cursor, bsum, stats, nb, N);
    k_scatter_gemm1<<<ngemm + nsc, 256>>>(ei, cursor, csr, E, ngemm,
                                          x, whi, h16, dis, N);

    // ================= Layer 1 gather (F=128) =================
    k_gather16<128><<<cdiv((long long)N * 16, 256), 256>>>(
        rowptr, deg, csr, h16, dis, b1, agg, stats, N);

    // ================= Layer 2: 128 -> 64 =================
    k_mma_gemm<64><<<ngemm, 256>>>(agg, whi + W2_OFF, h16, dis, N, 128,
                                   stats, g1, bt1);
    k_gather16<64><<<cdiv((long long)N * 8, 256), 256>>>(
        rowptr, deg, csr, h16, dis, b2, agg, stats + ST2, N);

    // ================= Layer 3: 64 -> 32 =================
    k_mma_gemm<32><<<ngemm, 256>>>(agg, whi + W3_OFF, h16, dis, N, 64,
                                   stats + ST2, g2, bt2);
    k_gather16<32><<<cdiv((long long)N * 4, 256), 256>>>(
        rowptr, deg, csr, h16, dis, b3, agg, stats + ST3, N);

    // ================= Final FC: 32 -> 1 (in-kernel BN + ReLU) =================
    k_final_fc<<<cdiv((long long)N * 32, 256), 256>>>(agg, stats + ST3, g3, bt3,
                                                      Wfc, bfc, out, N);
}